// round 10
// baseline (speedup 1.0000x reference)
#include <cuda_runtime.h>
#include <cuda_bf16.h>
#include <math.h>

#define N_NODES 100000
#define N_EDGES 3200000
#define HID 25
#define HPAD 32
#define NH 5
#define MH 50
#define MHP 52
#define ASTRIDE 64
#define SCAN_B 98
#define NODEB 391
#define KP 56
#define NP 56
#define SSTR 57

typedef unsigned long long ull;

// ---------------- static device scratch (zero-initialized at module load) ----------------
__device__ __align__(16) float  g_hn [N_NODES * HPAD];
__device__ __align__(16) float  g_q  [N_NODES * HPAD];
__device__ __align__(16) float  g_k  [N_NODES * HPAD];
__device__ __align__(16) float  g_v  [N_NODES * HPAD];
__device__ __align__(16) float  g_sk [N_NODES * HPAD];
__device__ __align__(16) float  g_A  [N_NODES * ASTRIDE];
__device__ __align__(16) float  g_B  [N_NODES * ASTRIDE];
__device__ int    g_deg[N_NODES];          // invariant: zero at kernel_launch entry
__device__ int    g_off[N_NODES + 1];
__device__ int    g_cur[N_NODES];
__device__ int    g_bsum[SCAN_B];
__device__ float4 g_pay[N_EDGES];

__device__ __forceinline__ float gelu_f(float x) {
    return 0.5f * x * (1.0f + erff(x * 0.70710678118654752440f));
}
__device__ __forceinline__ float tf32_trunc(float x) {
    return __uint_as_float(__float_as_uint(x) & 0xffffe000u);
}
__device__ __forceinline__ void mma_tf32(float d[4],
                                         unsigned a0, unsigned a1, unsigned a2, unsigned a3,
                                         unsigned b0, unsigned b1) {
    asm volatile(
        "mma.sync.aligned.m16n8k8.row.col.f32.tf32.tf32.f32 "
        "{%0,%1,%2,%3}, {%4,%5,%6,%7}, {%8,%9}, {%0,%1,%2,%3};"
        : "+f"(d[0]), "+f"(d[1]), "+f"(d[2]), "+f"(d[3])
        : "r"(a0), "r"(a1), "r"(a2), "r"(a3), "r"(b0), "r"(b1));
}

// ---------------- launch 1: fused node-init + edge degree count ----------------
__global__ __launch_bounds__(256) void k_prep(
    const float* __restrict__ x, const float* __restrict__ token,
    const float* __restrict__ ilW, const float* __restrict__ ilb,
    const float* __restrict__ W0, const int* __restrict__ ei)
{
    int gid = blockIdx.x * 256 + threadIdx.x;
    if (gid < N_EDGES) atomicAdd(&g_deg[ei[N_EDGES + gid]], 1);
    if (blockIdx.x >= NODEB) return;

    __shared__ __align__(16) float sIl[6 * 28];
    __shared__ float sIb[28];
    __shared__ __align__(16) float sW0[12 * MHP];
    for (int t = threadIdx.x; t < 6 * 28; t += 256) {
        int i = t / 28, j = t % 28;
        sIl[t] = (j < HID) ? ilW[i * HID + j] : 0.f;
    }
    for (int t = threadIdx.x; t < 28; t += 256) sIb[t] = (t < HID) ? ilb[t] : 0.f;
    for (int t = threadIdx.x; t < 12 * MHP; t += 256) {
        int i = t / MHP, j = t % MHP;
        sW0[t] = (j < MH) ? W0[i * MH + j] : 0.f;
    }
    __syncthreads();
    int n = gid;
    if (n >= N_NODES) return;
    float xt[6];
    xt[0] = x[n];
#pragma unroll
    for (int i = 0; i < 5; i++) xt[1 + i] = token[n * 5 + i];

    {
        float acc[28];
#pragma unroll
        for (int j = 0; j < 28; j++) acc[j] = sIb[j];
#pragma unroll
        for (int i = 0; i < 6; i++) {
            float xi = xt[i];
#pragma unroll
            for (int j = 0; j < 28; j++) acc[j] += xi * sIl[i * 28 + j];
        }
        float4* ho = (float4*)(g_hn + (size_t)n * HPAD);
#pragma unroll
        for (int j4 = 0; j4 < 7; j4++)
            ho[j4] = make_float4(acc[j4 * 4], acc[j4 * 4 + 1], acc[j4 * 4 + 2], acc[j4 * 4 + 3]);
        ho[7] = make_float4(0.f, 0.f, 0.f, 0.f);
    }
    {
        float acc[MHP];
#pragma unroll
        for (int j = 0; j < MHP; j++) acc[j] = 0.f;
#pragma unroll
        for (int i = 0; i < 6; i++) {
            float xi = xt[i];
#pragma unroll
            for (int j = 0; j < MHP; j++) acc[j] += xi * sW0[i * MHP + j];
        }
        float4* ao = (float4*)(g_A + (size_t)n * ASTRIDE);
#pragma unroll
        for (int j4 = 0; j4 < 13; j4++)
            ao[j4] = make_float4(acc[j4 * 4], acc[j4 * 4 + 1], acc[j4 * 4 + 2], acc[j4 * 4 + 3]);
#pragma unroll
        for (int j = 0; j < MHP; j++) acc[j] = 0.f;
#pragma unroll
        for (int i = 0; i < 6; i++) {
            float xi = xt[i];
#pragma unroll
            for (int j = 0; j < MHP; j++) acc[j] += xi * sW0[(6 + i) * MHP + j];
        }
        float4* bo = (float4*)(g_B + (size_t)n * ASTRIDE);
#pragma unroll
        for (int j4 = 0; j4 < 13; j4++)
            bo[j4] = make_float4(acc[j4 * 4], acc[j4 * 4 + 1], acc[j4 * 4 + 2], acc[j4 * 4 + 3]);
    }
}

// ---------------- launch 2/3: scan ----------------
__global__ void k_scan1() {
    __shared__ int s[1024];
    int i = blockIdx.x * 1024 + threadIdx.x;
    int v = (i < N_NODES) ? g_deg[i] : 0;
    s[threadIdx.x] = v;
    __syncthreads();
    for (int st = 1; st < 1024; st <<= 1) {
        int t = (threadIdx.x >= st) ? s[threadIdx.x - st] : 0;
        __syncthreads();
        s[threadIdx.x] += t;
        __syncthreads();
    }
    if (i < N_NODES) g_off[i + 1] = s[threadIdx.x];
    if (threadIdx.x == 1023) g_bsum[blockIdx.x] = s[1023];
}

__global__ void k_scan3() {
    __shared__ int pre;
    if (threadIdx.x < 32) {
        int lane = threadIdx.x;
        int tot = 0;
#pragma unroll
        for (int j = 0; j < 4; j++) {
            int idx = lane * 4 + j;
            tot += (idx < SCAN_B && idx < (int)blockIdx.x) ? g_bsum[idx] : 0;
        }
        int run = tot;
#pragma unroll
        for (int off = 1; off < 32; off <<= 1) {
            int t = __shfl_up_sync(0xffffffffu, run, off);
            if (lane >= off) run += t;
        }
        if (lane == 31) pre = run;
    }
    __syncthreads();
    int i = blockIdx.x * 1024 + threadIdx.x;
    if (i < N_NODES) {
        int off = g_off[i + 1] + pre;
        g_off[i + 1] = off;
        g_cur[i] = off - g_deg[i];
    }
    if (blockIdx.x == 0 && threadIdx.x == 0) g_off[0] = 0;
}

__global__ void k_zero() {
    int i = blockIdx.x * blockDim.x + threadIdx.x;
    if (i < N_NODES) g_deg[i] = 0;
}

// ---------------- launch 4 (profiled): edge MLP via tf32 tensor cores ----------------
__global__ __launch_bounds__(128, 4) void k_mlp(
    const float* __restrict__ W0, const float* __restrict__ b0,
    const float* __restrict__ W1, const float* __restrict__ b1,
    const float* __restrict__ W2, const float* __restrict__ b2,
    const float* __restrict__ W3, const float* __restrict__ b3,
    const float* __restrict__ ea_arr, const float* __restrict__ gum,
    const int* __restrict__ ei)
{
    __shared__ __align__(16) float sW1s[KP * NP];
    __shared__ __align__(16) float sW2s[KP * NP];
    __shared__ __align__(16) float sW0c[NP], sb0[NP], sb1[NP], sb2[NP];
    __shared__ __align__(16) float sW3[112];
    __shared__ float sb3[2];
    __shared__ __align__(16) float stage[64 * SSTR];

    for (int t = threadIdx.x; t < KP * NP; t += 128) {
        int i = t / NP, j = t % NP;
        float w1 = 0.f, w2 = 0.f;
        if (i < MH && j < MH) { w1 = W1[i * MH + j]; w2 = W2[i * MH + j]; }
        sW1s[t] = w1; sW2s[t] = w2;
    }
    for (int t = threadIdx.x; t < NP; t += 128) {
        sW0c[t] = (t < MH) ? W0[12 * MH + t] : 0.f;
        sb0[t]  = (t < MH) ? b0[t] : 0.f;
        sb1[t]  = (t < MH) ? b1[t] : 0.f;
        sb2[t]  = (t < MH) ? b2[t] : 0.f;
        sW3[2 * t]     = (t < MH) ? W3[t * 2 + 0] : 0.f;
        sW3[2 * t + 1] = (t < MH) ? W3[t * 2 + 1] : 0.f;
    }
    if (threadIdx.x < 2) sb3[threadIdx.x] = b3[threadIdx.x];
    __syncthreads();

    const int tid = threadIdx.x;
    const int eBase = blockIdx.x * 64;

    {   // layer 0: two threads per edge
        int r = tid >> 1, half = tid & 1;
        int e = eBase + r;
        int src = ei[e], dst = ei[N_EDGES + e];
        float ea = ea_arr[e];
        const float4* Ar  = (const float4*)(g_A + (size_t)src * ASTRIDE) + half * 7;
        const float4* Br  = (const float4*)(g_B + (size_t)dst * ASTRIDE) + half * 7;
        const float4* b0p = (const float4*)sb0  + half * 7;
        const float4* wcp = (const float4*)sW0c + half * 7;
        float* srow = stage + r * SSTR + half * 28;
#pragma unroll
        for (int j4 = 0; j4 < 7; j4++) {
            float4 av = Ar[j4], bv = Br[j4], bb = b0p[j4], wc = wcp[j4];
            srow[j4 * 4 + 0] = gelu_f(bb.x + av.x + bv.x + ea * wc.x);
            srow[j4 * 4 + 1] = gelu_f(bb.y + av.y + bv.y + ea * wc.y);
            srow[j4 * 4 + 2] = gelu_f(bb.z + av.z + bv.z + ea * wc.z);
            srow[j4 * 4 + 3] = gelu_f(bb.w + av.w + bv.w + ea * wc.w);
        }
    }
    __syncwarp();

    const int w = tid >> 5, lane = tid & 31;
    const int gr = lane >> 2, tg = lane & 3;
    float* Sw = stage + (w * 16) * SSTR;
    const float* Wl[2] = { sW1s, sW2s };
    const float* bl[2] = { sb1, sb2 };

    for (int L = 0; L < 2; L++) {
        const float* Ws = Wl[L];
        float d[7][4];
#pragma unroll
        for (int nn = 0; nn < 7; nn++)
#pragma unroll
            for (int q = 0; q < 4; q++) d[nn][q] = 0.f;

#pragma unroll
        for (int kk = 0; kk < 7; kk++) {
            int c0 = kk * 8 + tg;
            float x0 = Sw[gr * SSTR + c0];
            float x1 = Sw[(gr + 8) * SSTR + c0];
            float x2 = Sw[gr * SSTR + c0 + 4];
            float x3 = Sw[(gr + 8) * SSTR + c0 + 4];
            float h0 = tf32_trunc(x0), h1 = tf32_trunc(x1);
            float h2 = tf32_trunc(x2), h3 = tf32_trunc(x3);
            unsigned ah0 = __float_as_uint(h0), ah1 = __float_as_uint(h1);
            unsigned ah2 = __float_as_uint(h2), ah3 = __float_as_uint(h3);
            unsigned al0 = __float_as_uint(tf32_trunc(x0 - h0));
            unsigned al1 = __float_as_uint(tf32_trunc(x1 - h1));
            unsigned al2 = __float_as_uint(tf32_trunc(x2 - h2));
            unsigned al3 = __float_as_uint(tf32_trunc(x3 - h3));
#pragma unroll
            for (int nn = 0; nn < 7; nn++) {
                float bf0 = Ws[(kk * 8 + tg) * NP + nn * 8 + gr];
                float bf1 = Ws[(kk * 8 + tg + 4) * NP + nn * 8 + gr];
                float bh0f = tf32_trunc(bf0), bh1f = tf32_trunc(bf1);
                unsigned bh0 = __float_as_uint(bh0f), bh1 = __float_as_uint(bh1f);
                unsigned bl0 = __float_as_uint(tf32_trunc(bf0 - bh0f));
                unsigned bl1 = __float_as_uint(tf32_trunc(bf1 - bh1f));
                mma_tf32(d[nn], ah0, ah1, ah2, ah3, bh0, bh1);
                mma_tf32(d[nn], al0, al1, al2, al3, bh0, bh1);
                mma_tf32(d[nn], ah0, ah1, ah2, ah3, bl0, bl1);
            }
        }
        __syncwarp();
#pragma unroll
        for (int nn = 0; nn < 7; nn++) {
            int cA = nn * 8 + 2 * tg, cB = cA + 1;
            float bA = bl[L][cA], bB = bl[L][cB];
            Sw[gr * SSTR + cA]       = gelu_f(d[nn][0] + bA);
            Sw[gr * SSTR + cB]       = gelu_f(d[nn][1] + bB);
            Sw[(gr + 8) * SSTR + cA] = gelu_f(d[nn][2] + bA);
            Sw[(gr + 8) * SSTR + cB] = gelu_f(d[nn][3] + bB);
        }
        __syncwarp();
    }

    {   // logits (50 -> 2), lane pairs share an edge
        int r = w * 16 + (lane >> 1);
        int half = lane & 1;
        const float* hrow = stage + r * SSTR + half * 25;
        float l0 = 0.f, l1 = 0.f;
#pragma unroll
        for (int i = 0; i < 25; i++) {
            float h = hrow[i];
            int j = half * 25 + i;
            l0 += h * sW3[2 * j];
            l1 += h * sW3[2 * j + 1];
        }
        l0 += __shfl_xor_sync(0xffffffffu, l0, 1);
        l1 += __shfl_xor_sync(0xffffffffu, l1, 1);
        if (half == 0) {
            int e = eBase + r;
            float g0 = gum[2 * e], g1 = gum[2 * e + 1];
            float ev = (l1 + sb3[1] + g1 > l0 + sb3[0] + g0) ? 1.f : 0.f;
            int src = ei[e], dst = ei[N_EDGES + e];
            float ea = ea_arr[e];
            int pos = atomicAdd(&g_cur[dst], 1);
            g_pay[pos] = make_float4(__int_as_float(src), ea, ev, 0.f);
        }
    }
}

// ---------------- f32x2 helpers for node kernels ----------------
__device__ __forceinline__ ull splat2(float x) {
    ull r; unsigned xi = __float_as_uint(x);
    asm("mov.b64 %0, {%1, %1};" : "=l"(r) : "r"(xi));
    return r;
}
__device__ __forceinline__ ull fma2(ull a, ull b, ull c) {
    ull d; asm("fma.rn.f32x2 %0, %1, %2, %3;" : "=l"(d) : "l"(a), "l"(b), "l"(c));
    return d;
}

// ---------------- per-layer node transforms: q, k, v, skip ----------------
__global__ __launch_bounds__(128) void k_qkv(
    const float* __restrict__ Wq, const float* __restrict__ bq,
    const float* __restrict__ Wk, const float* __restrict__ bk,
    const float* __restrict__ Wv, const float* __restrict__ bv,
    const float* __restrict__ Ws, const float* __restrict__ bs, int l)
{
    __shared__ __align__(16) float sW[4][25 * 28];
    __shared__ __align__(16) float sb[4][28];
    const float* Wl[4] = { Wq + l * 625, Wk + l * 625, Wv + l * 625, Ws + l * 625 };
    const float* bl[4] = { bq + l * 25,  bk + l * 25,  bv + l * 25,  bs + l * 25 };
    for (int m = 0; m < 4; m++) {
        for (int t = threadIdx.x; t < 25 * 28; t += 128) {
            int i = t / 28, j = t % 28;
            sW[m][t] = (j < 25) ? Wl[m][i * 25 + j] : 0.f;
        }
        for (int t = threadIdx.x; t < 28; t += 128)
            sb[m][t] = (t < 25) ? bl[m][t] : 0.f;
    }
    __syncthreads();
    int n = blockIdx.x * 128 + threadIdx.x;
    if (n >= N_NODES) return;
    float hv[25];
#pragma unroll
    for (int c = 0; c < 25; c++) hv[c] = g_hn[(size_t)n * HPAD + c];
    float* outs[4] = { g_q + (size_t)n * HPAD, g_k + (size_t)n * HPAD,
                       g_v + (size_t)n * HPAD, g_sk + (size_t)n * HPAD };
#pragma unroll
    for (int m = 0; m < 4; m++) {
        ull acc[14];
        const ull* sbp = (const ull*)sb[m];
#pragma unroll
        for (int j2 = 0; j2 < 14; j2++) acc[j2] = sbp[j2];
#pragma unroll 5
        for (int i = 0; i < 25; i++) {
            ull xi2 = splat2(hv[i]);
            const ulonglong2* wv = (const ulonglong2*)(&sW[m][i * 28]);
#pragma unroll
            for (int j4 = 0; j4 < 7; j4++) {
                ulonglong2 w4 = wv[j4];
                acc[2 * j4]     = fma2(xi2, w4.x, acc[2 * j4]);
                acc[2 * j4 + 1] = fma2(xi2, w4.y, acc[2 * j4 + 1]);
            }
        }
        ull* o = (ull*)outs[m];
#pragma unroll
        for (int j2 = 0; j2 < 14; j2++) o[j2] = acc[j2];
    }
}

// ---------------- attention: one warp per node; direct softmax + affine-e factorization.
// e_c = be_c + ea*We0_c + ev*We1_c is affine in (ea, ev), so:
//   score: q.(k+e) = q.k + [q.be + ea*(q.We0) + ev*(q.We1)]   (3 per-node constants)
//   agg:   sum ex*(v+e) = sum ex*v + be*sum(ex) + We0*sum(ex*ea) + We1*sum(ex*ev)
// -> per-edge work is just q.k, exp, ex*v, and 3 scalar accumulations.
__global__ __launch_bounds__(128, 4) void k_attn(const float* __restrict__ We,
                                                 const float* __restrict__ be_, int l)
{
    __shared__ float sWe0[28], sWe1[28], sbe[28];
    if (threadIdx.x < 28) {
        int c = threadIdx.x;
        sWe0[c] = (c < 25) ? We[l * 50 + c]      : 0.f;
        sWe1[c] = (c < 25) ? We[l * 50 + 25 + c] : 0.f;
        sbe[c]  = (c < 25) ? be_[l * 25 + c]     : 0.f;
    }
    __syncthreads();
    int warp = threadIdx.x >> 5, lane = threadIdx.x & 31;
    int n = blockIdx.x * 4 + warp;
    if (n >= N_NODES) return;

    const float scale = 0.44721359549995794f;  // 1/sqrt(5)
    int beg = g_off[n], end = g_off[n + 1];

    float q[28];                                // pre-scaled by 1/sqrt(C)
    {
        const float4* qr = (const float4*)(g_q + (size_t)n * HPAD);
#pragma unroll
        for (int c4 = 0; c4 < 7; c4++) {
            float4 t = qr[c4];
            q[c4 * 4]     = t.x * scale; q[c4 * 4 + 1] = t.y * scale;
            q[c4 * 4 + 2] = t.z * scale; q[c4 * 4 + 3] = t.w * scale;
        }
    }
    // per-node score constants: qbe[h] = q_h.be_h, qW0[h] = q_h.We0_h, qW1[h] = q_h.We1_h
    float qbe[NH], qW0[NH], qW1[NH];
#pragma unroll
    for (int hh = 0; hh < NH; hh++) { qbe[hh] = 0.f; qW0[hh] = 0.f; qW1[hh] = 0.f; }
#pragma unroll
    for (int c = 0; c < 25; c++) {
        int hh = c / 5;
        qbe[hh] += q[c] * sbe[c];
        qW0[hh] += q[c] * sWe0[c];
        qW1[hh] += q[c] * sWe1[c];
    }

    float acc[25], d[NH], S2[NH], S3[NH];
#pragma unroll
    for (int c = 0; c < 25; c++) acc[c] = 0.f;
#pragma unroll
    for (int hh = 0; hh < NH; hh++) { d[hh] = 0.f; S2[hh] = 0.f; S3[hh] = 0.f; }

    for (int base = beg; base < end; base += 32) {
        int idx = base + lane;
        if (idx < end) {
            float4 p = g_pay[idx];
            int src = __float_as_int(p.x);
            float eav = p.y, evv = p.z;
            const float4* kr = (const float4*)(g_k + (size_t)src * HPAD);
            const float4* vr = (const float4*)(g_v + (size_t)src * HPAD);
            float kk[28], vv[28];
#pragma unroll
            for (int c4 = 0; c4 < 7; c4++) {
                float4 t = kr[c4];
                kk[c4 * 4] = t.x; kk[c4 * 4 + 1] = t.y; kk[c4 * 4 + 2] = t.z; kk[c4 * 4 + 3] = t.w;
            }
#pragma unroll
            for (int c4 = 0; c4 < 7; c4++) {
                float4 t = vr[c4];
                vv[c4 * 4] = t.x; vv[c4 * 4 + 1] = t.y; vv[c4 * 4 + 2] = t.z; vv[c4 * 4 + 3] = t.w;
            }
            float al[NH] = {0.f, 0.f, 0.f, 0.f, 0.f};
#pragma unroll
            for (int c = 0; c < 25; c++) al[c / 5] += q[c] * kk[c];
            float ex[NH];
#pragma unroll
            for (int hh = 0; hh < NH; hh++) {
                ex[hh] = __expf(al[hh] + qbe[hh] + eav * qW0[hh] + evv * qW1[hh]);
                d[hh]  += ex[hh];
                S2[hh] += ex[hh] * eav;
                S3[hh] += ex[hh] * evv;
            }
#pragma unroll
            for (int c = 0; c < 25; c++) acc[c] += ex[c / 5] * vv[c];
        }
    }
    // fold the affine-e message terms in per-lane (linear, so valid pre-reduction)
#pragma unroll
    for (int c = 0; c < 25; c++) {
        int hh = c / 5;
        acc[c] += d[hh] * sbe[c] + S2[hh] * sWe0[c] + S3[hh] * sWe1[c];
    }
#pragma unroll
    for (int hh = 0; hh < NH; hh++)
#pragma unroll
        for (int off = 16; off >= 1; off >>= 1)
            d[hh] += __shfl_xor_sync(0xffffffffu, d[hh], off);
#pragma unroll
    for (int c = 0; c < 25; c++)
#pragma unroll
        for (int off = 16; off >= 1; off >>= 1)
            acc[c] += __shfl_xor_sync(0xffffffffu, acc[c], off);
    if (lane == 0) {
#pragma unroll
        for (int c = 0; c < 25; c++)
            g_hn[(size_t)n * HPAD + c] =
                acc[c] / (d[c / 5] + 1e-16f) + g_sk[(size_t)n * HPAD + c];
    }
}

__global__ void k_out(const float* __restrict__ oW, const float* __restrict__ ob,
                      float* __restrict__ out) {
    __shared__ float sw[25];
    __shared__ float sb0;
    if (threadIdx.x < 25) sw[threadIdx.x] = oW[threadIdx.x];
    if (threadIdx.x == 0) sb0 = ob[0];
    __syncthreads();
    int n = blockIdx.x * blockDim.x + threadIdx.x;
    if (n >= N_NODES) return;
    float z = sb0;
#pragma unroll
    for (int c = 0; c < 25; c++) z += g_hn[(size_t)n * HPAD + c] * sw[c];
    out[n] = 1.f / (1.f + __expf(-z));
}

// ---------------- launcher ----------------
extern "C" void kernel_launch(void* const* d_in, const int* in_sizes, int n_in,
                              void* d_out, int out_size) {
    const float* x     = (const float*)d_in[0];
    const float* token = (const float*)d_in[1];
    const float* ea    = (const float*)d_in[2];
    const float* gum   = (const float*)d_in[3];
    const int* ei;
    int pb;
    if (in_sizes[4] == 2 * N_EDGES) {
        ei = (const int*)d_in[4];
        pb = 5;
    } else {
        ei = (const int*)d_in[n_in - 1];
        pb = 4;
    }
    const float* W0  = (const float*)d_in[pb + 0];
    const float* b0  = (const float*)d_in[pb + 1];
    const float* W1  = (const float*)d_in[pb + 2];
    const float* b1  = (const float*)d_in[pb + 3];
    const float* W2  = (const float*)d_in[pb + 4];
    const float* b2  = (const float*)d_in[pb + 5];
    const float* W3  = (const float*)d_in[pb + 6];
    const float* b3  = (const float*)d_in[pb + 7];
    const float* ilW = (const float*)d_in[pb + 8];
    const float* ilb = (const float*)d_in[pb + 9];
    const float* Wq  = (const float*)d_in[pb + 10];
    const float* bq  = (const float*)d_in[pb + 11];
    const float* Wk  = (const float*)d_in[pb + 12];
    const float* bk  = (const float*)d_in[pb + 13];
    const float* Wv  = (const float*)d_in[pb + 14];
    const float* bv  = (const float*)d_in[pb + 15];
    const float* We  = (const float*)d_in[pb + 16];
    const float* be  = (const float*)d_in[pb + 17];
    const float* Wsk = (const float*)d_in[pb + 18];
    const float* bsk = (const float*)d_in[pb + 19];
    const float* oW  = (const float*)d_in[pb + 20];
    const float* ob  = (const float*)d_in[pb + 21];

    int eb = (N_EDGES + 255) / 256;

    k_prep<<<eb, 256>>>(x, token, ilW, ilb, W0, ei);                       // 1
    k_scan1<<<SCAN_B, 1024>>>();                                          // 2
    k_scan3<<<SCAN_B, 1024>>>();                                          // 3
    k_mlp<<<N_EDGES / 64, 128>>>(W0, b0, W1, b1, W2, b2,
                                 W3, b3, ea, gum, ei);                    // 4 (profiled)
    k_zero<<<(N_NODES + 255) / 256, 256>>>();                             // 5
    for (int l = 0; l < 3; l++) {
        k_qkv<<<(N_NODES + 127) / 128, 128>>>(Wq, bq, Wk, bk, Wv, bv, Wsk, bsk, l);
        k_attn<<<(N_NODES + 3) / 4, 128>>>(We, be, l);
    }
    k_out<<<(N_NODES + 255) / 256, 256>>>(oW, ob, (float*)d_out);
}

// round 11
// speedup vs baseline: 1.1005x; 1.1005x over previous
#include <cuda_runtime.h>
#include <cuda_bf16.h>
#include <math.h>

#define N_NODES 100000
#define N_EDGES 3200000
#define HID 25
#define HPAD 32
#define NH 5
#define MH 50
#define MHP 52
#define ASTRIDE 64
#define SCAN_B 98
#define NODEB 391
#define KP 56
#define NP 56
#define SSTR 57

typedef unsigned long long ull;

// ---------------- static device scratch (zero-initialized at module load) ----------------
__device__ __align__(16) float  g_hn [N_NODES * HPAD];
__device__ __align__(16) float  g_q  [N_NODES * HPAD];
__device__ __align__(16) float  g_k  [N_NODES * HPAD];
__device__ __align__(16) float  g_v  [N_NODES * HPAD];
__device__ __align__(16) float  g_sk [N_NODES * HPAD];
__device__ __align__(16) float  g_A  [N_NODES * ASTRIDE];
__device__ __align__(16) float  g_B  [N_NODES * ASTRIDE];
__device__ int    g_deg[N_NODES];          // invariant: zero at kernel_launch entry
__device__ int    g_off[N_NODES + 1];
__device__ int    g_cur[N_NODES];
__device__ int    g_bsum[SCAN_B];
__device__ float4 g_pay[N_EDGES];

__device__ __forceinline__ float gelu_f(float x) {
    return 0.5f * x * (1.0f + erff(x * 0.70710678118654752440f));
}
__device__ __forceinline__ float tf32_trunc(float x) {
    return __uint_as_float(__float_as_uint(x) & 0xffffe000u);
}
__device__ __forceinline__ void mma_tf32(float d[4],
                                         unsigned a0, unsigned a1, unsigned a2, unsigned a3,
                                         unsigned b0, unsigned b1) {
    asm volatile(
        "mma.sync.aligned.m16n8k8.row.col.f32.tf32.tf32.f32 "
        "{%0,%1,%2,%3}, {%4,%5,%6,%7}, {%8,%9}, {%0,%1,%2,%3};"
        : "+f"(d[0]), "+f"(d[1]), "+f"(d[2]), "+f"(d[3])
        : "r"(a0), "r"(a1), "r"(a2), "r"(a3), "r"(b0), "r"(b1));
}

// ---------------- launch 1: fused node-init + edge degree count ----------------
__global__ __launch_bounds__(256) void k_prep(
    const float* __restrict__ x, const float* __restrict__ token,
    const float* __restrict__ ilW, const float* __restrict__ ilb,
    const float* __restrict__ W0, const int* __restrict__ ei)
{
    int gid = blockIdx.x * 256 + threadIdx.x;
    if (gid < N_EDGES) atomicAdd(&g_deg[ei[N_EDGES + gid]], 1);
    if (blockIdx.x >= NODEB) return;

    __shared__ __align__(16) float sIl[6 * 28];
    __shared__ float sIb[28];
    __shared__ __align__(16) float sW0[12 * MHP];
    for (int t = threadIdx.x; t < 6 * 28; t += 256) {
        int i = t / 28, j = t % 28;
        sIl[t] = (j < HID) ? ilW[i * HID + j] : 0.f;
    }
    for (int t = threadIdx.x; t < 28; t += 256) sIb[t] = (t < HID) ? ilb[t] : 0.f;
    for (int t = threadIdx.x; t < 12 * MHP; t += 256) {
        int i = t / MHP, j = t % MHP;
        sW0[t] = (j < MH) ? W0[i * MH + j] : 0.f;
    }
    __syncthreads();
    int n = gid;
    if (n >= N_NODES) return;
    float xt[6];
    xt[0] = x[n];
#pragma unroll
    for (int i = 0; i < 5; i++) xt[1 + i] = token[n * 5 + i];

    {
        float acc[28];
#pragma unroll
        for (int j = 0; j < 28; j++) acc[j] = sIb[j];
#pragma unroll
        for (int i = 0; i < 6; i++) {
            float xi = xt[i];
#pragma unroll
            for (int j = 0; j < 28; j++) acc[j] += xi * sIl[i * 28 + j];
        }
        float4* ho = (float4*)(g_hn + (size_t)n * HPAD);
#pragma unroll
        for (int j4 = 0; j4 < 7; j4++)
            ho[j4] = make_float4(acc[j4 * 4], acc[j4 * 4 + 1], acc[j4 * 4 + 2], acc[j4 * 4 + 3]);
        ho[7] = make_float4(0.f, 0.f, 0.f, 0.f);
    }
    {
        float acc[MHP];
#pragma unroll
        for (int j = 0; j < MHP; j++) acc[j] = 0.f;
#pragma unroll
        for (int i = 0; i < 6; i++) {
            float xi = xt[i];
#pragma unroll
            for (int j = 0; j < MHP; j++) acc[j] += xi * sW0[i * MHP + j];
        }
        float4* ao = (float4*)(g_A + (size_t)n * ASTRIDE);
#pragma unroll
        for (int j4 = 0; j4 < 13; j4++)
            ao[j4] = make_float4(acc[j4 * 4], acc[j4 * 4 + 1], acc[j4 * 4 + 2], acc[j4 * 4 + 3]);
#pragma unroll
        for (int j = 0; j < MHP; j++) acc[j] = 0.f;
#pragma unroll
        for (int i = 0; i < 6; i++) {
            float xi = xt[i];
#pragma unroll
            for (int j = 0; j < MHP; j++) acc[j] += xi * sW0[(6 + i) * MHP + j];
        }
        float4* bo = (float4*)(g_B + (size_t)n * ASTRIDE);
#pragma unroll
        for (int j4 = 0; j4 < 13; j4++)
            bo[j4] = make_float4(acc[j4 * 4], acc[j4 * 4 + 1], acc[j4 * 4 + 2], acc[j4 * 4 + 3]);
    }
}

// ---------------- launch 2/3: scan ----------------
__global__ void k_scan1() {
    __shared__ int s[1024];
    int i = blockIdx.x * 1024 + threadIdx.x;
    int v = (i < N_NODES) ? g_deg[i] : 0;
    s[threadIdx.x] = v;
    __syncthreads();
    for (int st = 1; st < 1024; st <<= 1) {
        int t = (threadIdx.x >= st) ? s[threadIdx.x - st] : 0;
        __syncthreads();
        s[threadIdx.x] += t;
        __syncthreads();
    }
    if (i < N_NODES) g_off[i + 1] = s[threadIdx.x];
    if (threadIdx.x == 1023) g_bsum[blockIdx.x] = s[1023];
}

// adds block prefix, emits g_cur, and re-zeroes g_deg (its last consumer)
__global__ void k_scan3() {
    __shared__ int pre;
    if (threadIdx.x < 32) {
        int lane = threadIdx.x;
        int tot = 0;
#pragma unroll
        for (int j = 0; j < 4; j++) {
            int idx = lane * 4 + j;
            tot += (idx < SCAN_B && idx < (int)blockIdx.x) ? g_bsum[idx] : 0;
        }
        int run = tot;
#pragma unroll
        for (int off = 1; off < 32; off <<= 1) {
            int t = __shfl_up_sync(0xffffffffu, run, off);
            if (lane >= off) run += t;
        }
        if (lane == 31) pre = run;
    }
    __syncthreads();
    int i = blockIdx.x * 1024 + threadIdx.x;
    if (i < N_NODES) {
        int off = g_off[i + 1] + pre;
        g_off[i + 1] = off;
        g_cur[i] = off - g_deg[i];
        g_deg[i] = 0;                       // restore invariant for next call
    }
    if (blockIdx.x == 0 && threadIdx.x == 0) g_off[0] = 0;
}

// ---------------- launch 4 (profiled): edge MLP via tf32 tensor cores ----------------
__global__ __launch_bounds__(128, 4) void k_mlp(
    const float* __restrict__ W0, const float* __restrict__ b0,
    const float* __restrict__ W1, const float* __restrict__ b1,
    const float* __restrict__ W2, const float* __restrict__ b2,
    const float* __restrict__ W3, const float* __restrict__ b3,
    const float* __restrict__ ea_arr, const float* __restrict__ gum,
    const int* __restrict__ ei)
{
    __shared__ __align__(16) float sW1s[KP * NP];
    __shared__ __align__(16) float sW2s[KP * NP];
    __shared__ __align__(16) float sW0c[NP], sb0[NP], sb1[NP], sb2[NP];
    __shared__ __align__(16) float sW3[112];
    __shared__ float sb3[2];
    __shared__ __align__(16) float stage[64 * SSTR];

    for (int t = threadIdx.x; t < KP * NP; t += 128) {
        int i = t / NP, j = t % NP;
        float w1 = 0.f, w2 = 0.f;
        if (i < MH && j < MH) { w1 = W1[i * MH + j]; w2 = W2[i * MH + j]; }
        sW1s[t] = w1; sW2s[t] = w2;
    }
    for (int t = threadIdx.x; t < NP; t += 128) {
        sW0c[t] = (t < MH) ? W0[12 * MH + t] : 0.f;
        sb0[t]  = (t < MH) ? b0[t] : 0.f;
        sb1[t]  = (t < MH) ? b1[t] : 0.f;
        sb2[t]  = (t < MH) ? b2[t] : 0.f;
        sW3[2 * t]     = (t < MH) ? W3[t * 2 + 0] : 0.f;
        sW3[2 * t + 1] = (t < MH) ? W3[t * 2 + 1] : 0.f;
    }
    if (threadIdx.x < 2) sb3[threadIdx.x] = b3[threadIdx.x];
    __syncthreads();

    const int tid = threadIdx.x;
    const int eBase = blockIdx.x * 64;

    {   // layer 0: two threads per edge
        int r = tid >> 1, half = tid & 1;
        int e = eBase + r;
        int src = ei[e], dst = ei[N_EDGES + e];
        float ea = ea_arr[e];
        const float4* Ar  = (const float4*)(g_A + (size_t)src * ASTRIDE) + half * 7;
        const float4* Br  = (const float4*)(g_B + (size_t)dst * ASTRIDE) + half * 7;
        const float4* b0p = (const float4*)sb0  + half * 7;
        const float4* wcp = (const float4*)sW0c + half * 7;
        float* srow = stage + r * SSTR + half * 28;
#pragma unroll
        for (int j4 = 0; j4 < 7; j4++) {
            float4 av = Ar[j4], bv = Br[j4], bb = b0p[j4], wc = wcp[j4];
            srow[j4 * 4 + 0] = gelu_f(bb.x + av.x + bv.x + ea * wc.x);
            srow[j4 * 4 + 1] = gelu_f(bb.y + av.y + bv.y + ea * wc.y);
            srow[j4 * 4 + 2] = gelu_f(bb.z + av.z + bv.z + ea * wc.z);
            srow[j4 * 4 + 3] = gelu_f(bb.w + av.w + bv.w + ea * wc.w);
        }
    }
    __syncwarp();

    const int w = tid >> 5, lane = tid & 31;
    const int gr = lane >> 2, tg = lane & 3;
    float* Sw = stage + (w * 16) * SSTR;
    const float* Wl[2] = { sW1s, sW2s };
    const float* bl[2] = { sb1, sb2 };

    for (int L = 0; L < 2; L++) {
        const float* Ws = Wl[L];
        float d[7][4];
#pragma unroll
        for (int nn = 0; nn < 7; nn++)
#pragma unroll
            for (int q = 0; q < 4; q++) d[nn][q] = 0.f;

#pragma unroll
        for (int kk = 0; kk < 7; kk++) {
            int c0 = kk * 8 + tg;
            float x0 = Sw[gr * SSTR + c0];
            float x1 = Sw[(gr + 8) * SSTR + c0];
            float x2 = Sw[gr * SSTR + c0 + 4];
            float x3 = Sw[(gr + 8) * SSTR + c0 + 4];
            float h0 = tf32_trunc(x0), h1 = tf32_trunc(x1);
            float h2 = tf32_trunc(x2), h3 = tf32_trunc(x3);
            unsigned ah0 = __float_as_uint(h0), ah1 = __float_as_uint(h1);
            unsigned ah2 = __float_as_uint(h2), ah3 = __float_as_uint(h3);
            unsigned al0 = __float_as_uint(tf32_trunc(x0 - h0));
            unsigned al1 = __float_as_uint(tf32_trunc(x1 - h1));
            unsigned al2 = __float_as_uint(tf32_trunc(x2 - h2));
            unsigned al3 = __float_as_uint(tf32_trunc(x3 - h3));
#pragma unroll
            for (int nn = 0; nn < 7; nn++) {
                float bf0 = Ws[(kk * 8 + tg) * NP + nn * 8 + gr];
                float bf1 = Ws[(kk * 8 + tg + 4) * NP + nn * 8 + gr];
                float bh0f = tf32_trunc(bf0), bh1f = tf32_trunc(bf1);
                unsigned bh0 = __float_as_uint(bh0f), bh1 = __float_as_uint(bh1f);
                unsigned bl0 = __float_as_uint(tf32_trunc(bf0 - bh0f));
                unsigned bl1 = __float_as_uint(tf32_trunc(bf1 - bh1f));
                mma_tf32(d[nn], ah0, ah1, ah2, ah3, bh0, bh1);
                mma_tf32(d[nn], al0, al1, al2, al3, bh0, bh1);
                mma_tf32(d[nn], ah0, ah1, ah2, ah3, bl0, bl1);
            }
        }
        __syncwarp();
#pragma unroll
        for (int nn = 0; nn < 7; nn++) {
            int cA = nn * 8 + 2 * tg, cB = cA + 1;
            float bA = bl[L][cA], bB = bl[L][cB];
            Sw[gr * SSTR + cA]       = gelu_f(d[nn][0] + bA);
            Sw[gr * SSTR + cB]       = gelu_f(d[nn][1] + bB);
            Sw[(gr + 8) * SSTR + cA] = gelu_f(d[nn][2] + bA);
            Sw[(gr + 8) * SSTR + cB] = gelu_f(d[nn][3] + bB);
        }
        __syncwarp();
    }

    {   // logits (50 -> 2), lane pairs share an edge
        int r = w * 16 + (lane >> 1);
        int half = lane & 1;
        const float* hrow = stage + r * SSTR + half * 25;
        float l0 = 0.f, l1 = 0.f;
#pragma unroll
        for (int i = 0; i < 25; i++) {
            float h = hrow[i];
            int j = half * 25 + i;
            l0 += h * sW3[2 * j];
            l1 += h * sW3[2 * j + 1];
        }
        l0 += __shfl_xor_sync(0xffffffffu, l0, 1);
        l1 += __shfl_xor_sync(0xffffffffu, l1, 1);
        if (half == 0) {
            int e = eBase + r;
            float g0 = gum[2 * e], g1 = gum[2 * e + 1];
            float ev = (l1 + sb3[1] + g1 > l0 + sb3[0] + g0) ? 1.f : 0.f;
            int src = ei[e], dst = ei[N_EDGES + e];
            float ea = ea_arr[e];
            int pos = atomicAdd(&g_cur[dst], 1);
            g_pay[pos] = make_float4(__int_as_float(src), ea, ev, 0.f);
        }
    }
}

// ---------------- f32x2 helpers for node kernels ----------------
__device__ __forceinline__ ull splat2(float x) {
    ull r; unsigned xi = __float_as_uint(x);
    asm("mov.b64 %0, {%1, %1};" : "=l"(r) : "r"(xi));
    return r;
}
__device__ __forceinline__ ull fma2(ull a, ull b, ull c) {
    ull d; asm("fma.rn.f32x2 %0, %1, %2, %3;" : "=l"(d) : "l"(a), "l"(b), "l"(c));
    return d;
}

// ---------------- per-layer node transforms: q, k, v, skip ----------------
__global__ __launch_bounds__(128) void k_qkv(
    const float* __restrict__ Wq, const float* __restrict__ bq,
    const float* __restrict__ Wk, const float* __restrict__ bk,
    const float* __restrict__ Wv, const float* __restrict__ bv,
    const float* __restrict__ Ws, const float* __restrict__ bs, int l)
{
    __shared__ __align__(16) float sW[4][25 * 28];
    __shared__ __align__(16) float sb[4][28];
    const float* Wl[4] = { Wq + l * 625, Wk + l * 625, Wv + l * 625, Ws + l * 625 };
    const float* bl[4] = { bq + l * 25,  bk + l * 25,  bv + l * 25,  bs + l * 25 };
    for (int m = 0; m < 4; m++) {
        for (int t = threadIdx.x; t < 25 * 28; t += 128) {
            int i = t / 28, j = t % 28;
            sW[m][t] = (j < 25) ? Wl[m][i * 25 + j] : 0.f;
        }
        for (int t = threadIdx.x; t < 28; t += 128)
            sb[m][t] = (t < 25) ? bl[m][t] : 0.f;
    }
    __syncthreads();
    int n = blockIdx.x * 128 + threadIdx.x;
    if (n >= N_NODES) return;
    float hv[25];
#pragma unroll
    for (int c = 0; c < 25; c++) hv[c] = g_hn[(size_t)n * HPAD + c];
    float* outs[4] = { g_q + (size_t)n * HPAD, g_k + (size_t)n * HPAD,
                       g_v + (size_t)n * HPAD, g_sk + (size_t)n * HPAD };
#pragma unroll
    for (int m = 0; m < 4; m++) {
        ull acc[14];
        const ull* sbp = (const ull*)sb[m];
#pragma unroll
        for (int j2 = 0; j2 < 14; j2++) acc[j2] = sbp[j2];
#pragma unroll 5
        for (int i = 0; i < 25; i++) {
            ull xi2 = splat2(hv[i]);
            const ulonglong2* wv = (const ulonglong2*)(&sW[m][i * 28]);
#pragma unroll
            for (int j4 = 0; j4 < 7; j4++) {
                ulonglong2 w4 = wv[j4];
                acc[2 * j4]     = fma2(xi2, w4.x, acc[2 * j4]);
                acc[2 * j4 + 1] = fma2(xi2, w4.y, acc[2 * j4 + 1]);
            }
        }
        ull* o = (ull*)outs[m];
#pragma unroll
        for (int j2 = 0; j2 < 14; j2++) o[j2] = acc[j2];
    }
}

// ---------------- attention: one warp per node; direct softmax + affine-e factorization.
// (round-9 structure + factorization; launch_bounds (128,3) — NO reg cap / spills)
__global__ __launch_bounds__(128, 3) void k_attn(const float* __restrict__ We,
                                                 const float* __restrict__ be_, int l)
{
    __shared__ float sWe0[28], sWe1[28], sbe[28];
    if (threadIdx.x < 28) {
        int c = threadIdx.x;
        sWe0[c] = (c < 25) ? We[l * 50 + c]      : 0.f;
        sWe1[c] = (c < 25) ? We[l * 50 + 25 + c] : 0.f;
        sbe[c]  = (c < 25) ? be_[l * 25 + c]     : 0.f;
    }
    __syncthreads();
    int warp = threadIdx.x >> 5, lane = threadIdx.x & 31;
    int n = blockIdx.x * 4 + warp;
    if (n >= N_NODES) return;

    const float scale = 0.44721359549995794f;  // 1/sqrt(5)
    int beg = g_off[n], end = g_off[n + 1];

    float q[28];                                // pre-scaled by 1/sqrt(C)
    {
        const float4* qr = (const float4*)(g_q + (size_t)n * HPAD);
#pragma unroll
        for (int c4 = 0; c4 < 7; c4++) {
            float4 t = qr[c4];
            q[c4 * 4]     = t.x * scale; q[c4 * 4 + 1] = t.y * scale;
            q[c4 * 4 + 2] = t.z * scale; q[c4 * 4 + 3] = t.w * scale;
        }
    }
    float qbe[NH], qW0[NH], qW1[NH];
#pragma unroll
    for (int hh = 0; hh < NH; hh++) { qbe[hh] = 0.f; qW0[hh] = 0.f; qW1[hh] = 0.f; }
#pragma unroll
    for (int c = 0; c < 25; c++) {
        int hh = c / 5;
        qbe[hh] += q[c] * sbe[c];
        qW0[hh] += q[c] * sWe0[c];
        qW1[hh] += q[c] * sWe1[c];
    }

    float acc[25], d[NH], S2[NH], S3[NH];
#pragma unroll
    for (int c = 0; c < 25; c++) acc[c] = 0.f;
#pragma unroll
    for (int hh = 0; hh < NH; hh++) { d[hh] = 0.f; S2[hh] = 0.f; S3[hh] = 0.f; }

    for (int base = beg; base < end; base += 32) {
        int idx = base + lane;
        if (idx < end) {
            float4 p = g_pay[idx];
            int src = __float_as_int(p.x);
            float eav = p.y, evv = p.z;
            const float4* kr = (const float4*)(g_k + (size_t)src * HPAD);
            const float4* vr = (const float4*)(g_v + (size_t)src * HPAD);
            float kk[28], vv[28];
#pragma unroll
            for (int c4 = 0; c4 < 7; c4++) {
                float4 t = kr[c4];
                kk[c4 * 4] = t.x; kk[c4 * 4 + 1] = t.y; kk[c4 * 4 + 2] = t.z; kk[c4 * 4 + 3] = t.w;
            }
#pragma unroll
            for (int c4 = 0; c4 < 7; c4++) {
                float4 t = vr[c4];
                vv[c4 * 4] = t.x; vv[c4 * 4 + 1] = t.y; vv[c4 * 4 + 2] = t.z; vv[c4 * 4 + 3] = t.w;
            }
            float al[NH] = {0.f, 0.f, 0.f, 0.f, 0.f};
#pragma unroll
            for (int c = 0; c < 25; c++) al[c / 5] += q[c] * kk[c];
            float ex[NH];
#pragma unroll
            for (int hh = 0; hh < NH; hh++) {
                ex[hh] = __expf(al[hh] + qbe[hh] + eav * qW0[hh] + evv * qW1[hh]);
                d[hh]  += ex[hh];
                S2[hh] += ex[hh] * eav;
                S3[hh] += ex[hh] * evv;
            }
#pragma unroll
            for (int c = 0; c < 25; c++) acc[c] += ex[c / 5] * vv[c];
        }
    }
    // fold the affine-e message terms in per-lane (linear, so valid pre-reduction)
#pragma unroll
    for (int c = 0; c < 25; c++) {
        int hh = c / 5;
        acc[c] += d[hh] * sbe[c] + S2[hh] * sWe0[c] + S3[hh] * sWe1[c];
    }
#pragma unroll
    for (int hh = 0; hh < NH; hh++)
#pragma unroll
        for (int off = 16; off >= 1; off >>= 1)
            d[hh] += __shfl_xor_sync(0xffffffffu, d[hh], off);
#pragma unroll
    for (int c = 0; c < 25; c++)
#pragma unroll
        for (int off = 16; off >= 1; off >>= 1)
            acc[c] += __shfl_xor_sync(0xffffffffu, acc[c], off);
    if (lane == 0) {
#pragma unroll
        for (int c = 0; c < 25; c++)
            g_hn[(size_t)n * HPAD + c] =
                acc[c] / (d[c / 5] + 1e-16f) + g_sk[(size_t)n * HPAD + c];
    }
}

__global__ void k_out(const float* __restrict__ oW, const float* __restrict__ ob,
                      float* __restrict__ out) {
    __shared__ float sw[25];
    __shared__ float sb0;
    if (threadIdx.x < 25) sw[threadIdx.x] = oW[threadIdx.x];
    if (threadIdx.x == 0) sb0 = ob[0];
    __syncthreads();
    int n = blockIdx.x * blockDim.x + threadIdx.x;
    if (n >= N_NODES) return;
    float z = sb0;
#pragma unroll
    for (int c = 0; c < 25; c++) z += g_hn[(size_t)n * HPAD + c] * sw[c];
    out[n] = 1.f / (1.f + __expf(-z));
}

// ---------------- launcher ----------------
extern "C" void kernel_launch(void* const* d_in, const int* in_sizes, int n_in,
                              void* d_out, int out_size) {
    const float* x     = (const float*)d_in[0];
    const float* token = (const float*)d_in[1];
    const float* ea    = (const float*)d_in[2];
    const float* gum   = (const float*)d_in[3];
    const int* ei;
    int pb;
    if (in_sizes[4] == 2 * N_EDGES) {
        ei = (const int*)d_in[4];
        pb = 5;
    } else {
        ei = (const int*)d_in[n_in - 1];
        pb = 4;
    }
    const float* W0  = (const float*)d_in[pb + 0];
    const float* b0  = (const float*)d_in[pb + 1];
    const float* W1  = (const float*)d_in[pb + 2];
    const float* b1  = (const float*)d_in[pb + 3];
    const float* W2  = (const float*)d_in[pb + 4];
    const float* b2  = (const float*)d_in[pb + 5];
    const float* W3  = (const float*)d_in[pb + 6];
    const float* b3  = (const float*)d_in[pb + 7];
    const float* ilW = (const float*)d_in[pb + 8];
    const float* ilb = (const float*)d_in[pb + 9];
    const float* Wq  = (const float*)d_in[pb + 10];
    const float* bq  = (const float*)d_in[pb + 11];
    const float* Wk  = (const float*)d_in[pb + 12];
    const float* bk  = (const float*)d_in[pb + 13];
    const float* Wv  = (const float*)d_in[pb + 14];
    const float* bv  = (const float*)d_in[pb + 15];
    const float* We  = (const float*)d_in[pb + 16];
    const float* be  = (const float*)d_in[pb + 17];
    const float* Wsk = (const float*)d_in[pb + 18];
    const float* bsk = (const float*)d_in[pb + 19];
    const float* oW  = (const float*)d_in[pb + 20];
    const float* ob  = (const float*)d_in[pb + 21];

    int eb = (N_EDGES + 255) / 256;

    k_prep<<<eb, 256>>>(x, token, ilW, ilb, W0, ei);                       // 1
    k_scan1<<<SCAN_B, 1024>>>();                                          // 2
    k_scan3<<<SCAN_B, 1024>>>();                                          // 3 (also re-zeroes g_deg)
    k_mlp<<<N_EDGES / 64, 128>>>(W0, b0, W1, b1, W2, b2,
                                 W3, b3, ea, gum, ei);                    // 4 (profiled)
    for (int l = 0; l < 3; l++) {
        k_qkv<<<(N_NODES + 127) / 128, 128>>>(Wq, bq, Wk, bk, Wv, bv, Wsk, bsk, l);
        k_attn<<<(N_NODES + 3) / 4, 128>>>(We, be, l);
    }
    k_out<<<(N_NODES + 255) / 256, 256>>>(oW, ob, (float*)d_out);
}

// round 14
// speedup vs baseline: 1.1166x; 1.0146x over previous
#include <cuda_runtime.h>
#include <cuda_bf16.h>
#include <math.h>

#define N_NODES 100000
#define N_EDGES 3200000
#define HID 25
#define HPAD 32
#define NH 5
#define MH 50
#define MHP 52
#define ASTRIDE 64
#define SCAN_B 98
#define NODEB 391
#define KP 56
#define NP 56
#define SSTR 57

typedef unsigned long long ull;

// ---------------- static device scratch (zero-initialized at module load) ----------------
__device__ __align__(16) float  g_hn [N_NODES * HPAD];
__device__ __align__(16) float  g_q  [N_NODES * HPAD];
__device__ __align__(16) float  g_k  [N_NODES * HPAD];
__device__ __align__(16) float  g_v  [N_NODES * HPAD];
__device__ __align__(16) float  g_sk [N_NODES * HPAD];
__device__ __align__(16) float  g_A  [N_NODES * ASTRIDE];
__device__ __align__(16) float  g_B  [N_NODES * ASTRIDE];
__device__ int    g_deg[N_NODES];          // invariant: zero at kernel_launch entry
__device__ int    g_off[N_NODES + 1];
__device__ int    g_cur[N_NODES];
__device__ int    g_bsum[SCAN_B];
__device__ float4 g_pay[N_EDGES];

__device__ __forceinline__ float gelu_f(float x) {
    return 0.5f * x * (1.0f + erff(x * 0.70710678118654752440f));
}
__device__ __forceinline__ float tf32_trunc(float x) {
    return __uint_as_float(__float_as_uint(x) & 0xffffe000u);
}
__device__ __forceinline__ void mma_tf32(float d[4],
                                         unsigned a0, unsigned a1, unsigned a2, unsigned a3,
                                         unsigned b0, unsigned b1) {
    asm volatile(
        "mma.sync.aligned.m16n8k8.row.col.f32.tf32.tf32.f32 "
        "{%0,%1,%2,%3}, {%4,%5,%6,%7}, {%8,%9}, {%0,%1,%2,%3};"
        : "+f"(d[0]), "+f"(d[1]), "+f"(d[2]), "+f"(d[3])
        : "r"(a0), "r"(a1), "r"(a2), "r"(a3), "r"(b0), "r"(b1));
}

// ---------------- launch 1: fused node-init + edge degree count ----------------
__global__ __launch_bounds__(256) void k_prep(
    const float* __restrict__ x, const float* __restrict__ token,
    const float* __restrict__ ilW, const float* __restrict__ ilb,
    const float* __restrict__ W0, const int* __restrict__ ei)
{
    int gid = blockIdx.x * 256 + threadIdx.x;
    if (gid < N_EDGES) atomicAdd(&g_deg[ei[N_EDGES + gid]], 1);
    if (blockIdx.x >= NODEB) return;

    __shared__ __align__(16) float sIl[6 * 28];
    __shared__ float sIb[28];
    __shared__ __align__(16) float sW0[12 * MHP];
    for (int t = threadIdx.x; t < 6 * 28; t += 256) {
        int i = t / 28, j = t % 28;
        sIl[t] = (j < HID) ? ilW[i * HID + j] : 0.f;
    }
    for (int t = threadIdx.x; t < 28; t += 256) sIb[t] = (t < HID) ? ilb[t] : 0.f;
    for (int t = threadIdx.x; t < 12 * MHP; t += 256) {
        int i = t / MHP, j = t % MHP;
        sW0[t] = (j < MH) ? W0[i * MH + j] : 0.f;
    }
    __syncthreads();
    int n = gid;
    if (n >= N_NODES) return;
    float xt[6];
    xt[0] = x[n];
#pragma unroll
    for (int i = 0; i < 5; i++) xt[1 + i] = token[n * 5 + i];

    {
        float acc[28];
#pragma unroll
        for (int j = 0; j < 28; j++) acc[j] = sIb[j];
#pragma unroll
        for (int i = 0; i < 6; i++) {
            float xi = xt[i];
#pragma unroll
            for (int j = 0; j < 28; j++) acc[j] += xi * sIl[i * 28 + j];
        }
        float4* ho = (float4*)(g_hn + (size_t)n * HPAD);
#pragma unroll
        for (int j4 = 0; j4 < 7; j4++)
            ho[j4] = make_float4(acc[j4 * 4], acc[j4 * 4 + 1], acc[j4 * 4 + 2], acc[j4 * 4 + 3]);
        ho[7] = make_float4(0.f, 0.f, 0.f, 0.f);
    }
    {
        float acc[MHP];
#pragma unroll
        for (int j = 0; j < MHP; j++) acc[j] = 0.f;
#pragma unroll
        for (int i = 0; i < 6; i++) {
            float xi = xt[i];
#pragma unroll
            for (int j = 0; j < MHP; j++) acc[j] += xi * sW0[i * MHP + j];
        }
        float4* ao = (float4*)(g_A + (size_t)n * ASTRIDE);
#pragma unroll
        for (int j4 = 0; j4 < 13; j4++)
            ao[j4] = make_float4(acc[j4 * 4], acc[j4 * 4 + 1], acc[j4 * 4 + 2], acc[j4 * 4 + 3]);
#pragma unroll
        for (int j = 0; j < MHP; j++) acc[j] = 0.f;
#pragma unroll
        for (int i = 0; i < 6; i++) {
            float xi = xt[i];
#pragma unroll
            for (int j = 0; j < MHP; j++) acc[j] += xi * sW0[(6 + i) * MHP + j];
        }
        float4* bo = (float4*)(g_B + (size_t)n * ASTRIDE);
#pragma unroll
        for (int j4 = 0; j4 < 13; j4++)
            bo[j4] = make_float4(acc[j4 * 4], acc[j4 * 4 + 1], acc[j4 * 4 + 2], acc[j4 * 4 + 3]);
    }
}

// ---------------- launch 2/3: scan ----------------
__global__ void k_scan1() {
    __shared__ int s[1024];
    int i = blockIdx.x * 1024 + threadIdx.x;
    int v = (i < N_NODES) ? g_deg[i] : 0;
    s[threadIdx.x] = v;
    __syncthreads();
    for (int st = 1; st < 1024; st <<= 1) {
        int t = (threadIdx.x >= st) ? s[threadIdx.x - st] : 0;
        __syncthreads();
        s[threadIdx.x] += t;
        __syncthreads();
    }
    if (i < N_NODES) g_off[i + 1] = s[threadIdx.x];
    if (threadIdx.x == 1023) g_bsum[blockIdx.x] = s[1023];
}

// adds block prefix, emits g_cur, and re-zeroes g_deg (its last consumer)
__global__ void k_scan3() {
    __shared__ int pre;
    if (threadIdx.x < 32) {
        int lane = threadIdx.x;
        int tot = 0;
#pragma unroll
        for (int j = 0; j < 4; j++) {
            int idx = lane * 4 + j;
            tot += (idx < SCAN_B && idx < (int)blockIdx.x) ? g_bsum[idx] : 0;
        }
        int run = tot;
#pragma unroll
        for (int off = 1; off < 32; off <<= 1) {
            int t = __shfl_up_sync(0xffffffffu, run, off);
            if (lane >= off) run += t;
        }
        if (lane == 31) pre = run;
    }
    __syncthreads();
    int i = blockIdx.x * 1024 + threadIdx.x;
    if (i < N_NODES) {
        int off = g_off[i + 1] + pre;
        g_off[i + 1] = off;
        g_cur[i] = off - g_deg[i];
        g_deg[i] = 0;
    }
    if (blockIdx.x == 0 && threadIdx.x == 0) g_off[0] = 0;
}

// ---------------- launch 4 (profiled): edge MLP via tf32 tensor cores ----------------
// Round-6/9 structure; lo residuals fed to HMMA untruncated (implicit tf32 read,
// validated in round 8 at rel_err 4.5e-8) — removes 6 LOP3 per inner step.
__global__ __launch_bounds__(128, 4) void k_mlp(
    const float* __restrict__ W0, const float* __restrict__ b0,
    const float* __restrict__ W1, const float* __restrict__ b1,
    const float* __restrict__ W2, const float* __restrict__ b2,
    const float* __restrict__ W3, const float* __restrict__ b3,
    const float* __restrict__ ea_arr, const float* __restrict__ gum,
    const int* __restrict__ ei)
{
    __shared__ __align__(16) float sW1s[KP * NP];
    __shared__ __align__(16) float sW2s[KP * NP];
    __shared__ __align__(16) float sW0c[NP], sb0[NP], sb1[NP], sb2[NP];
    __shared__ __align__(16) float sW3[112];
    __shared__ float sb3[2];
    __shared__ __align__(16) float stage[64 * SSTR];

    for (int t = threadIdx.x; t < KP * NP; t += 128) {
        int i = t / NP, j = t % NP;
        float w1 = 0.f, w2 = 0.f;
        if (i < MH && j < MH) { w1 = W1[i * MH + j]; w2 = W2[i * MH + j]; }
        sW1s[t] = w1; sW2s[t] = w2;
    }
    for (int t = threadIdx.x; t < NP; t += 128) {
        sW0c[t] = (t < MH) ? W0[12 * MH + t] : 0.f;
        sb0[t]  = (t < MH) ? b0[t] : 0.f;
        sb1[t]  = (t < MH) ? b1[t] : 0.f;
        sb2[t]  = (t < MH) ? b2[t] : 0.f;
        sW3[2 * t]     = (t < MH) ? W3[t * 2 + 0] : 0.f;
        sW3[2 * t + 1] = (t < MH) ? W3[t * 2 + 1] : 0.f;
    }
    if (threadIdx.x < 2) sb3[threadIdx.x] = b3[threadIdx.x];
    __syncthreads();

    const int tid = threadIdx.x;
    const int eBase = blockIdx.x * 64;

    {   // layer 0: two threads per edge
        int r = tid >> 1, half = tid & 1;
        int e = eBase + r;
        int src = ei[e], dst = ei[N_EDGES + e];
        float ea = ea_arr[e];
        const float4* Ar  = (const float4*)(g_A + (size_t)src * ASTRIDE) + half * 7;
        const float4* Br  = (const float4*)(g_B + (size_t)dst * ASTRIDE) + half * 7;
        const float4* b0p = (const float4*)sb0  + half * 7;
        const float4* wcp = (const float4*)sW0c + half * 7;
        float* srow = stage + r * SSTR + half * 28;
#pragma unroll
        for (int j4 = 0; j4 < 7; j4++) {
            float4 av = Ar[j4], bv = Br[j4], bb = b0p[j4], wc = wcp[j4];
            srow[j4 * 4 + 0] = gelu_f(bb.x + av.x + bv.x + ea * wc.x);
            srow[j4 * 4 + 1] = gelu_f(bb.y + av.y + bv.y + ea * wc.y);
            srow[j4 * 4 + 2] = gelu_f(bb.z + av.z + bv.z + ea * wc.z);
            srow[j4 * 4 + 3] = gelu_f(bb.w + av.w + bv.w + ea * wc.w);
        }
    }
    __syncwarp();

    const int w = tid >> 5, lane = tid & 31;
    const int gr = lane >> 2, tg = lane & 3;
    float* Sw = stage + (w * 16) * SSTR;
    const float* Wl[2] = { sW1s, sW2s };
    const float* bl[2] = { sb1, sb2 };

    for (int L = 0; L < 2; L++) {
        const float* Ws = Wl[L];
        float d[7][4];
#pragma unroll
        for (int nn = 0; nn < 7; nn++)
#pragma unroll
            for (int q = 0; q < 4; q++) d[nn][q] = 0.f;

#pragma unroll
        for (int kk = 0; kk < 7; kk++) {
            int c0 = kk * 8 + tg;
            float x0 = Sw[gr * SSTR + c0];
            float x1 = Sw[(gr + 8) * SSTR + c0];
            float x2 = Sw[gr * SSTR + c0 + 4];
            float x3 = Sw[(gr + 8) * SSTR + c0 + 4];
            float h0 = tf32_trunc(x0), h1 = tf32_trunc(x1);
            float h2 = tf32_trunc(x2), h3 = tf32_trunc(x3);
            unsigned ah0 = __float_as_uint(h0), ah1 = __float_as_uint(h1);
            unsigned ah2 = __float_as_uint(h2), ah3 = __float_as_uint(h3);
            // lo residuals un-truncated: HMMA truncates operands implicitly
            unsigned al0 = __float_as_uint(x0 - h0), al1 = __float_as_uint(x1 - h1);
            unsigned al2 = __float_as_uint(x2 - h2), al3 = __float_as_uint(x3 - h3);
#pragma unroll
            for (int nn = 0; nn < 7; nn++) {
                float bf0 = Ws[(kk * 8 + tg) * NP + nn * 8 + gr];
                float bf1 = Ws[(kk * 8 + tg + 4) * NP + nn * 8 + gr];
                float bh0f = tf32_trunc(bf0), bh1f = tf32_trunc(bf1);
                unsigned bh0 = __float_as_uint(bh0f), bh1 = __float_as_uint(bh1f);
                unsigned bl0 = __float_as_uint(bf0 - bh0f);
                unsigned bl1 = __float_as_uint(bf1 - bh1f);
                mma_tf32(d[nn], ah0, ah1, ah2, ah3, bh0, bh1);
                mma_tf32(d[nn], al0, al1, al2, al3, bh0, bh1);
                mma_tf32(d[nn], ah0, ah1, ah2, ah3, bl0, bl1);
            }
        }
        __syncwarp();
#pragma unroll
        for (int nn = 0; nn < 7; nn++) {
            int cA = nn * 8 + 2 * tg, cB = cA + 1;
            float bA = bl[L][cA], bB = bl[L][cB];
            Sw[gr * SSTR + cA]       = gelu_f(d[nn][0] + bA);
            Sw[gr * SSTR + cB]       = gelu_f(d[nn][1] + bB);
            Sw[(gr + 8) * SSTR + cA] = gelu_f(d[nn][2] + bA);
            Sw[(gr + 8) * SSTR + cB] = gelu_f(d[nn][3] + bB);
        }
        __syncwarp();
    }

    {   // logits (50 -> 2), lane pairs share an edge
        int r = w * 16 + (lane >> 1);
        int half = lane & 1;
        const float* hrow = stage + r * SSTR + half * 25;
        float l0 = 0.f, l1 = 0.f;
#pragma unroll
        for (int i = 0; i < 25; i++) {
            float h = hrow[i];
            int j = half * 25 + i;
            l0 += h * sW3[2 * j];
            l1 += h * sW3[2 * j + 1];
        }
        l0 += __shfl_xor_sync(0xffffffffu, l0, 1);
        l1 += __shfl_xor_sync(0xffffffffu, l1, 1);
        if (half == 0) {
            int e = eBase + r;
            float g0 = gum[2 * e], g1 = gum[2 * e + 1];
            float ev = (l1 + sb3[1] + g1 > l0 + sb3[0] + g0) ? 1.f : 0.f;
            int src = ei[e], dst = ei[N_EDGES + e];
            float ea = ea_arr[e];
            int pos = atomicAdd(&g_cur[dst], 1);
            g_pay[pos] = make_float4(__int_as_float(src), ea, ev, 0.f);
        }
    }
}

// ---------------- f32x2 helpers for node kernels ----------------
__device__ __forceinline__ ull splat2(float x) {
    ull r; unsigned xi = __float_as_uint(x);
    asm("mov.b64 %0, {%1, %1};" : "=l"(r) : "r"(xi));
    return r;
}
__device__ __forceinline__ ull fma2(ull a, ull b, ull c) {
    ull d; asm("fma.rn.f32x2 %0, %1, %2, %3;" : "=l"(d) : "l"(a), "l"(b), "l"(c));
    return d;
}

// ---------------- per-layer node transforms: q, k, v, skip ----------------
__global__ __launch_bounds__(128) void k_qkv(
    const float* __restrict__ Wq, const float* __restrict__ bq,
    const float* __restrict__ Wk, const float* __restrict__ bk,
    const float* __restrict__ Wv, const float* __restrict__ bv,
    const float* __restrict__ Ws, const float* __restrict__ bs, int l)
{
    __shared__ __align__(16) float sW[4][25 * 28];
    __shared__ __align__(16) float sb[4][28];
    const float* Wl[4] = { Wq + l * 625, Wk + l * 625, Wv + l * 625, Ws + l * 625 };
    const float* bl[4] = { bq + l * 25,  bk + l * 25,  bv + l * 25,  bs + l * 25 };
    for (int m = 0; m < 4; m++) {
        for (int t = threadIdx.x; t < 25 * 28; t += 128) {
            int i = t / 28, j = t % 28;
            sW[m][t] = (j < 25) ? Wl[m][i * 25 + j] : 0.f;
        }
        for (int t = threadIdx.x; t < 28; t += 128)
            sb[m][t] = (t < 25) ? bl[m][t] : 0.f;
    }
    __syncthreads();
    int n = blockIdx.x * 128 + threadIdx.x;
    if (n >= N_NODES) return;
    float hv[25];
#pragma unroll
    for (int c = 0; c < 25; c++) hv[c] = g_hn[(size_t)n * HPAD + c];
    float* outs[4] = { g_q + (size_t)n * HPAD, g_k + (size_t)n * HPAD,
                       g_v + (size_t)n * HPAD, g_sk + (size_t)n * HPAD };
#pragma unroll
    for (int m = 0; m < 4; m++) {
        ull acc[14];
        const ull* sbp = (const ull*)sb[m];
#pragma unroll
        for (int j2 = 0; j2 < 14; j2++) acc[j2] = sbp[j2];
#pragma unroll 5
        for (int i = 0; i < 25; i++) {
            ull xi2 = splat2(hv[i]);
            const ulonglong2* wv = (const ulonglong2*)(&sW[m][i * 28]);
#pragma unroll
            for (int j4 = 0; j4 < 7; j4++) {
                ulonglong2 w4 = wv[j4];
                acc[2 * j4]     = fma2(xi2, w4.x, acc[2 * j4]);
                acc[2 * j4 + 1] = fma2(xi2, w4.y, acc[2 * j4 + 1]);
            }
        }
        ull* o = (ull*)outs[m];
#pragma unroll
        for (int j2 = 0; j2 < 14; j2++) o[j2] = acc[j2];
    }
}

// ---------------- attention: one warp per node; direct softmax (exact round-9 version) ----------------
__global__ __launch_bounds__(128, 3) void k_attn(const float* __restrict__ We,
                                                 const float* __restrict__ be_, int l)
{
    __shared__ float sWe0[28], sWe1[28], sbe[28];
    if (threadIdx.x < 28) {
        int c = threadIdx.x;
        sWe0[c] = (c < 25) ? We[l * 50 + c]      : 0.f;
        sWe1[c] = (c < 25) ? We[l * 50 + 25 + c] : 0.f;
        sbe[c]  = (c < 25) ? be_[l * 25 + c]     : 0.f;
    }
    __syncthreads();
    int warp = threadIdx.x >> 5, lane = threadIdx.x & 31;
    int n = blockIdx.x * 4 + warp;
    if (n >= N_NODES) return;

    int beg = g_off[n], end = g_off[n + 1];
    float q[28];
    {
        const float4* qr = (const float4*)(g_q + (size_t)n * HPAD);
#pragma unroll
        for (int c4 = 0; c4 < 7; c4++) {
            float4 t = qr[c4];
            q[c4 * 4] = t.x; q[c4 * 4 + 1] = t.y; q[c4 * 4 + 2] = t.z; q[c4 * 4 + 3] = t.w;
        }
    }
    float acc[25], d[NH];
#pragma unroll
    for (int c = 0; c < 25; c++) acc[c] = 0.f;
#pragma unroll
    for (int hh = 0; hh < NH; hh++) d[hh] = 0.f;
    const float scale = 0.44721359549995794f;  // 1/sqrt(5)

    for (int base = beg; base < end; base += 32) {
        int idx = base + lane;
        if (idx < end) {
            float4 p = g_pay[idx];
            int src = __float_as_int(p.x);
            float eav = p.y, evv = p.z;
            const float4* kr = (const float4*)(g_k + (size_t)src * HPAD);
            const float4* vr = (const float4*)(g_v + (size_t)src * HPAD);
            float kk[28], vv[28];
#pragma unroll
            for (int c4 = 0; c4 < 7; c4++) {
                float4 t = kr[c4];
                kk[c4 * 4] = t.x; kk[c4 * 4 + 1] = t.y; kk[c4 * 4 + 2] = t.z; kk[c4 * 4 + 3] = t.w;
            }
#pragma unroll
            for (int c4 = 0; c4 < 7; c4++) {
                float4 t = vr[c4];
                vv[c4 * 4] = t.x; vv[c4 * 4 + 1] = t.y; vv[c4 * 4 + 2] = t.z; vv[c4 * 4 + 3] = t.w;
            }
            float al[NH] = {0.f, 0.f, 0.f, 0.f, 0.f};
#pragma unroll
            for (int c = 0; c < 25; c++) {
                float ee = sbe[c] + eav * sWe0[c] + evv * sWe1[c];
                al[c / 5] += q[c] * (kk[c] + ee);
            }
            float ex[NH];
#pragma unroll
            for (int hh = 0; hh < NH; hh++) {
                ex[hh] = __expf(al[hh] * scale);
                d[hh] += ex[hh];
            }
#pragma unroll
            for (int c = 0; c < 25; c++) {
                float ee = sbe[c] + eav * sWe0[c] + evv * sWe1[c];
                acc[c] += ex[c / 5] * (vv[c] + ee);
            }
        }
    }
#pragma unroll
    for (int hh = 0; hh < NH; hh++)
#pragma unroll
        for (int off = 16; off >= 1; off >>= 1)
            d[hh] += __shfl_xor_sync(0xffffffffu, d[hh], off);
#pragma unroll
    for (int c = 0; c < 25; c++)
#pragma unroll
        for (int off = 16; off >= 1; off >>= 1)
            acc[c] += __shfl_xor_sync(0xffffffffu, acc[c], off);
    if (lane == 0) {
#pragma unroll
        for (int c = 0; c < 25; c++)
            g_hn[(size_t)n * HPAD + c] =
                acc[c] / (d[c / 5] + 1e-16f) + g_sk[(size_t)n * HPAD + c];
    }
}

__global__ void k_out(const float* __restrict__ oW, const float* __restrict__ ob,
                      float* __restrict__ out) {
    __shared__ float sw[25];
    __shared__ float sb0;
    if (threadIdx.x < 25) sw[threadIdx.x] = oW[threadIdx.x];
    if (threadIdx.x == 0) sb0 = ob[0];
    __syncthreads();
    int n = blockIdx.x * blockDim.x + threadIdx.x;
    if (n >= N_NODES) return;
    float z = sb0;
#pragma unroll
    for (int c = 0; c < 25; c++) z += g_hn[(size_t)n * HPAD + c] * sw[c];
    out[n] = 1.f / (1.f + __expf(-z));
}

// ---------------- launcher ----------------
extern "C" void kernel_launch(void* const* d_in, const int* in_sizes, int n_in,
                              void* d_out, int out_size) {
    const float* x     = (const float*)d_in[0];
    const float* token = (const float*)d_in[1];
    const float* ea    = (const float*)d_in[2];
    const float* gum   = (const float*)d_in[3];
    const int* ei;
    int pb;
    if (in_sizes[4] == 2 * N_EDGES) {
        ei = (const int*)d_in[4];
        pb = 5;
    } else {
        ei = (const int*)d_in[n_in - 1];
        pb = 4;
    }
    const float* W0  = (const float*)d_in[pb + 0];
    const float* b0  = (const float*)d_in[pb + 1];
    const float* W1  = (const float*)d_in[pb + 2];
    const float* b1  = (const float*)d_in[pb + 3];
    const float* W2  = (const float*)d_in[pb + 4];
    const float* b2  = (const float*)d_in[pb + 5];
    const float* W3  = (const float*)d_in[pb + 6];
    const float* b3  = (const float*)d_in[pb + 7];
    const float* ilW = (const float*)d_in[pb + 8];
    const float* ilb = (const float*)d_in[pb + 9];
    const float* Wq  = (const float*)d_in[pb + 10];
    const float* bq  = (const float*)d_in[pb + 11];
    const float* Wk  = (const float*)d_in[pb + 12];
    const float* bk  = (const float*)d_in[pb + 13];
    const float* Wv  = (const float*)d_in[pb + 14];
    const float* bv  = (const float*)d_in[pb + 15];
    const float* We  = (const float*)d_in[pb + 16];
    const float* be  = (const float*)d_in[pb + 17];
    const float* Wsk = (const float*)d_in[pb + 18];
    const float* bsk = (const float*)d_in[pb + 19];
    const float* oW  = (const float*)d_in[pb + 20];
    const float* ob  = (const float*)d_in[pb + 21];

    int eb = (N_EDGES + 255) / 256;

    k_prep<<<eb, 256>>>(x, token, ilW, ilb, W0, ei);                       // 1
    k_scan1<<<SCAN_B, 1024>>>();                                          // 2
    k_scan3<<<SCAN_B, 1024>>>();                                          // 3 (also re-zeroes g_deg)
    k_mlp<<<N_EDGES / 64, 128>>>(W0, b0, W1, b1, W2, b2,
                                 W3, b3, ea, gum, ei);                    // 4 (profiled)
    for (int l = 0; l < 3; l++) {
        k_qkv<<<(N_NODES + 127) / 128, 128>>>(Wq, bq, Wk, bk, Wv, bv, Wsk, bsk, l);
        k_attn<<<(N_NODES + 3) / 4, 128>>>(We, be, l);
    }
    k_out<<<(N_NODES + 255) / 256, 256>>>(oW, ob, (float*)d_out);
}

// round 15
// speedup vs baseline: 1.1839x; 1.0603x over previous
#include <cuda_runtime.h>
#include <cuda_bf16.h>
#include <math.h>

#define N_NODES 100000
#define N_EDGES 3200000
#define HID 25
#define HPAD 32
#define NH 5
#define MH 50
#define MHP 52
#define ASTRIDE 64
#define SCAN_B 98
#define NODEB 391
#define KP 56
#define NP 56
#define SSTR 57

typedef unsigned long long ull;

// ---------------- static device scratch (zero-initialized at module load) ----------------
__device__ __align__(16) float  g_hn [N_NODES * HPAD];
__device__ __align__(16) float  g_q  [N_NODES * HPAD];
__device__ __align__(16) float  g_k  [N_NODES * HPAD];
__device__ __align__(16) float  g_v  [N_NODES * HPAD];
__device__ __align__(16) float  g_sk [N_NODES * HPAD];
__device__ __align__(16) float  g_A  [N_NODES * ASTRIDE];
__device__ __align__(16) float  g_B  [N_NODES * ASTRIDE];
__device__ int    g_deg[N_NODES];          // invariant: zero at kernel_launch entry
__device__ int    g_off[N_NODES + 1];
__device__ int    g_cur[N_NODES];
__device__ int    g_bsum[SCAN_B];
__device__ float4 g_pay[N_EDGES];

__device__ __forceinline__ float gelu_f(float x) {
    return 0.5f * x * (1.0f + erff(x * 0.70710678118654752440f));
}
__device__ __forceinline__ void mma_tf32(float d[4],
                                         unsigned a0, unsigned a1, unsigned a2, unsigned a3,
                                         unsigned b0, unsigned b1) {
    asm volatile(
        "mma.sync.aligned.m16n8k8.row.col.f32.tf32.tf32.f32 "
        "{%0,%1,%2,%3}, {%4,%5,%6,%7}, {%8,%9}, {%0,%1,%2,%3};"
        : "+f"(d[0]), "+f"(d[1]), "+f"(d[2]), "+f"(d[3])
        : "r"(a0), "r"(a1), "r"(a2), "r"(a3), "r"(b0), "r"(b1));
}

// ---------------- launch 1: fused node-init + edge degree count ----------------
__global__ __launch_bounds__(256) void k_prep(
    const float* __restrict__ x, const float* __restrict__ token,
    const float* __restrict__ ilW, const float* __restrict__ ilb,
    const float* __restrict__ W0, const int* __restrict__ ei)
{
    int gid = blockIdx.x * 256 + threadIdx.x;
    if (gid < N_EDGES) atomicAdd(&g_deg[ei[N_EDGES + gid]], 1);
    if (blockIdx.x >= NODEB) return;

    __shared__ __align__(16) float sIl[6 * 28];
    __shared__ float sIb[28];
    __shared__ __align__(16) float sW0[12 * MHP];
    for (int t = threadIdx.x; t < 6 * 28; t += 256) {
        int i = t / 28, j = t % 28;
        sIl[t] = (j < HID) ? ilW[i * HID + j] : 0.f;
    }
    for (int t = threadIdx.x; t < 28; t += 256) sIb[t] = (t < HID) ? ilb[t] : 0.f;
    for (int t = threadIdx.x; t < 12 * MHP; t += 256) {
        int i = t / MHP, j = t % MHP;
        sW0[t] = (j < MH) ? W0[i * MH + j] : 0.f;
    }
    __syncthreads();
    int n = gid;
    if (n >= N_NODES) return;
    float xt[6];
    xt[0] = x[n];
#pragma unroll
    for (int i = 0; i < 5; i++) xt[1 + i] = token[n * 5 + i];

    {
        float acc[28];
#pragma unroll
        for (int j = 0; j < 28; j++) acc[j] = sIb[j];
#pragma unroll
        for (int i = 0; i < 6; i++) {
            float xi = xt[i];
#pragma unroll
            for (int j = 0; j < 28; j++) acc[j] += xi * sIl[i * 28 + j];
        }
        float4* ho = (float4*)(g_hn + (size_t)n * HPAD);
#pragma unroll
        for (int j4 = 0; j4 < 7; j4++)
            ho[j4] = make_float4(acc[j4 * 4], acc[j4 * 4 + 1], acc[j4 * 4 + 2], acc[j4 * 4 + 3]);
        ho[7] = make_float4(0.f, 0.f, 0.f, 0.f);
    }
    {
        float acc[MHP];
#pragma unroll
        for (int j = 0; j < MHP; j++) acc[j] = 0.f;
#pragma unroll
        for (int i = 0; i < 6; i++) {
            float xi = xt[i];
#pragma unroll
            for (int j = 0; j < MHP; j++) acc[j] += xi * sW0[i * MHP + j];
        }
        float4* ao = (float4*)(g_A + (size_t)n * ASTRIDE);
#pragma unroll
        for (int j4 = 0; j4 < 13; j4++)
            ao[j4] = make_float4(acc[j4 * 4], acc[j4 * 4 + 1], acc[j4 * 4 + 2], acc[j4 * 4 + 3]);
#pragma unroll
        for (int j = 0; j < MHP; j++) acc[j] = 0.f;
#pragma unroll
        for (int i = 0; i < 6; i++) {
            float xi = xt[i];
#pragma unroll
            for (int j = 0; j < MHP; j++) acc[j] += xi * sW0[(6 + i) * MHP + j];
        }
        float4* bo = (float4*)(g_B + (size_t)n * ASTRIDE);
#pragma unroll
        for (int j4 = 0; j4 < 13; j4++)
            bo[j4] = make_float4(acc[j4 * 4], acc[j4 * 4 + 1], acc[j4 * 4 + 2], acc[j4 * 4 + 3]);
    }
}

// ---------------- launch 2/3: scan ----------------
__global__ void k_scan1() {
    __shared__ int s[1024];
    int i = blockIdx.x * 1024 + threadIdx.x;
    int v = (i < N_NODES) ? g_deg[i] : 0;
    s[threadIdx.x] = v;
    __syncthreads();
    for (int st = 1; st < 1024; st <<= 1) {
        int t = (threadIdx.x >= st) ? s[threadIdx.x - st] : 0;
        __syncthreads();
        s[threadIdx.x] += t;
        __syncthreads();
    }
    if (i < N_NODES) g_off[i + 1] = s[threadIdx.x];
    if (threadIdx.x == 1023) g_bsum[blockIdx.x] = s[1023];
}

// adds block prefix, emits g_cur, and re-zeroes g_deg (its last consumer)
__global__ void k_scan3() {
    __shared__ int pre;
    if (threadIdx.x < 32) {
        int lane = threadIdx.x;
        int tot = 0;
#pragma unroll
        for (int j = 0; j < 4; j++) {
            int idx = lane * 4 + j;
            tot += (idx < SCAN_B && idx < (int)blockIdx.x) ? g_bsum[idx] : 0;
        }
        int run = tot;
#pragma unroll
        for (int off = 1; off < 32; off <<= 1) {
            int t = __shfl_up_sync(0xffffffffu, run, off);
            if (lane >= off) run += t;
        }
        if (lane == 31) pre = run;
    }
    __syncthreads();
    int i = blockIdx.x * 1024 + threadIdx.x;
    if (i < N_NODES) {
        int off = g_off[i + 1] + pre;
        g_off[i + 1] = off;
        g_cur[i] = off - g_deg[i];
        g_deg[i] = 0;
    }
    if (blockIdx.x == 0 && threadIdx.x == 0) g_off[0] = 0;
}

// ---------------- launch 4 (profiled): edge MLP via SINGLE-PASS tf32 mma ----------------
// Output feeds only an argmax comparison; single tf32 mma (error ~1e-4 on logits
// vs O(1) Gumbel margins) flips only ~1e2/3.2M edges -> rel_err ~1e-5, far under
// the 1e-3 gate. No hi/lo splitting: HMMA truncates fp32 operands implicitly.
__global__ __launch_bounds__(128, 4) void k_mlp(
    const float* __restrict__ W0, const float* __restrict__ b0,
    const float* __restrict__ W1, const float* __restrict__ b1,
    const float* __restrict__ W2, const float* __restrict__ b2,
    const float* __restrict__ W3, const float* __restrict__ b3,
    const float* __restrict__ ea_arr, const float* __restrict__ gum,
    const int* __restrict__ ei)
{
    __shared__ __align__(16) float sW1s[KP * NP];
    __shared__ __align__(16) float sW2s[KP * NP];
    __shared__ __align__(16) float sW0c[NP], sb0[NP], sb1[NP], sb2[NP];
    __shared__ __align__(16) float sW3[112];
    __shared__ float sb3[2];
    __shared__ __align__(16) float stage[64 * SSTR];

    for (int t = threadIdx.x; t < KP * NP; t += 128) {
        int i = t / NP, j = t % NP;
        float w1 = 0.f, w2 = 0.f;
        if (i < MH && j < MH) { w1 = W1[i * MH + j]; w2 = W2[i * MH + j]; }
        sW1s[t] = w1; sW2s[t] = w2;
    }
    for (int t = threadIdx.x; t < NP; t += 128) {
        sW0c[t] = (t < MH) ? W0[12 * MH + t] : 0.f;
        sb0[t]  = (t < MH) ? b0[t] : 0.f;
        sb1[t]  = (t < MH) ? b1[t] : 0.f;
        sb2[t]  = (t < MH) ? b2[t] : 0.f;
        sW3[2 * t]     = (t < MH) ? W3[t * 2 + 0] : 0.f;
        sW3[2 * t + 1] = (t < MH) ? W3[t * 2 + 1] : 0.f;
    }
    if (threadIdx.x < 2) sb3[threadIdx.x] = b3[threadIdx.x];
    __syncthreads();

    const int tid = threadIdx.x;
    const int eBase = blockIdx.x * 64;

    {   // layer 0: two threads per edge
        int r = tid >> 1, half = tid & 1;
        int e = eBase + r;
        int src = ei[e], dst = ei[N_EDGES + e];
        float ea = ea_arr[e];
        const float4* Ar  = (const float4*)(g_A + (size_t)src * ASTRIDE) + half * 7;
        const float4* Br  = (const float4*)(g_B + (size_t)dst * ASTRIDE) + half * 7;
        const float4* b0p = (const float4*)sb0  + half * 7;
        const float4* wcp = (const float4*)sW0c + half * 7;
        float* srow = stage + r * SSTR + half * 28;
#pragma unroll
        for (int j4 = 0; j4 < 7; j4++) {
            float4 av = Ar[j4], bv = Br[j4], bb = b0p[j4], wc = wcp[j4];
            srow[j4 * 4 + 0] = gelu_f(bb.x + av.x + bv.x + ea * wc.x);
            srow[j4 * 4 + 1] = gelu_f(bb.y + av.y + bv.y + ea * wc.y);
            srow[j4 * 4 + 2] = gelu_f(bb.z + av.z + bv.z + ea * wc.z);
            srow[j4 * 4 + 3] = gelu_f(bb.w + av.w + bv.w + ea * wc.w);
        }
    }
    __syncwarp();

    const int w = tid >> 5, lane = tid & 31;
    const int gr = lane >> 2, tg = lane & 3;
    float* Sw = stage + (w * 16) * SSTR;
    const float* Wl[2] = { sW1s, sW2s };
    const float* bl[2] = { sb1, sb2 };

    for (int L = 0; L < 2; L++) {
        const float* Ws = Wl[L];
        float d[7][4];
#pragma unroll
        for (int nn = 0; nn < 7; nn++)
#pragma unroll
            for (int q = 0; q < 4; q++) d[nn][q] = 0.f;

#pragma unroll
        for (int kk = 0; kk < 7; kk++) {
            int c0 = kk * 8 + tg;
            unsigned a0 = __float_as_uint(Sw[gr * SSTR + c0]);
            unsigned a1 = __float_as_uint(Sw[(gr + 8) * SSTR + c0]);
            unsigned a2 = __float_as_uint(Sw[gr * SSTR + c0 + 4]);
            unsigned a3 = __float_as_uint(Sw[(gr + 8) * SSTR + c0 + 4]);
#pragma unroll
            for (int nn = 0; nn < 7; nn++) {
                unsigned b0v = __float_as_uint(Ws[(kk * 8 + tg) * NP + nn * 8 + gr]);
                unsigned b1v = __float_as_uint(Ws[(kk * 8 + tg + 4) * NP + nn * 8 + gr]);
                mma_tf32(d[nn], a0, a1, a2, a3, b0v, b1v);
            }
        }
        __syncwarp();
#pragma unroll
        for (int nn = 0; nn < 7; nn++) {
            int cA = nn * 8 + 2 * tg, cB = cA + 1;
            float bA = bl[L][cA], bB = bl[L][cB];
            Sw[gr * SSTR + cA]       = gelu_f(d[nn][0] + bA);
            Sw[gr * SSTR + cB]       = gelu_f(d[nn][1] + bB);
            Sw[(gr + 8) * SSTR + cA] = gelu_f(d[nn][2] + bA);
            Sw[(gr + 8) * SSTR + cB] = gelu_f(d[nn][3] + bB);
        }
        __syncwarp();
    }

    {   // logits (50 -> 2), lane pairs share an edge
        int r = w * 16 + (lane >> 1);
        int half = lane & 1;
        const float* hrow = stage + r * SSTR + half * 25;
        float l0 = 0.f, l1 = 0.f;
#pragma unroll
        for (int i = 0; i < 25; i++) {
            float h = hrow[i];
            int j = half * 25 + i;
            l0 += h * sW3[2 * j];
            l1 += h * sW3[2 * j + 1];
        }
        l0 += __shfl_xor_sync(0xffffffffu, l0, 1);
        l1 += __shfl_xor_sync(0xffffffffu, l1, 1);
        if (half == 0) {
            int e = eBase + r;
            float g0 = gum[2 * e], g1 = gum[2 * e + 1];
            float ev = (l1 + sb3[1] + g1 > l0 + sb3[0] + g0) ? 1.f : 0.f;
            int src = ei[e], dst = ei[N_EDGES + e];
            float ea = ea_arr[e];
            int pos = atomicAdd(&g_cur[dst], 1);
            g_pay[pos] = make_float4(__int_as_float(src), ea, ev, 0.f);
        }
    }
}

// ---------------- f32x2 helpers for node kernels ----------------
__device__ __forceinline__ ull splat2(float x) {
    ull r; unsigned xi = __float_as_uint(x);
    asm("mov.b64 %0, {%1, %1};" : "=l"(r) : "r"(xi));
    return r;
}
__device__ __forceinline__ ull fma2(ull a, ull b, ull c) {
    ull d; asm("fma.rn.f32x2 %0, %1, %2, %3;" : "=l"(d) : "l"(a), "l"(b), "l"(c));
    return d;
}

// ---------------- per-layer node transforms: q, k, v, skip ----------------
__global__ __launch_bounds__(128) void k_qkv(
    const float* __restrict__ Wq, const float* __restrict__ bq,
    const float* __restrict__ Wk, const float* __restrict__ bk,
    const float* __restrict__ Wv, const float* __restrict__ bv,
    const float* __restrict__ Ws, const float* __restrict__ bs, int l)
{
    __shared__ __align__(16) float sW[4][25 * 28];
    __shared__ __align__(16) float sb[4][28];
    const float* Wl[4] = { Wq + l * 625, Wk + l * 625, Wv + l * 625, Ws + l * 625 };
    const float* bl[4] = { bq + l * 25,  bk + l * 25,  bv + l * 25,  bs + l * 25 };
    for (int m = 0; m < 4; m++) {
        for (int t = threadIdx.x; t < 25 * 28; t += 128) {
            int i = t / 28, j = t % 28;
            sW[m][t] = (j < 25) ? Wl[m][i * 25 + j] : 0.f;
        }
        for (int t = threadIdx.x; t < 28; t += 128)
            sb[m][t] = (t < 25) ? bl[m][t] : 0.f;
    }
    __syncthreads();
    int n = blockIdx.x * 128 + threadIdx.x;
    if (n >= N_NODES) return;
    float hv[25];
#pragma unroll
    for (int c = 0; c < 25; c++) hv[c] = g_hn[(size_t)n * HPAD + c];
    float* outs[4] = { g_q + (size_t)n * HPAD, g_k + (size_t)n * HPAD,
                       g_v + (size_t)n * HPAD, g_sk + (size_t)n * HPAD };
#pragma unroll
    for (int m = 0; m < 4; m++) {
        ull acc[14];
        const ull* sbp = (const ull*)sb[m];
#pragma unroll
        for (int j2 = 0; j2 < 14; j2++) acc[j2] = sbp[j2];
#pragma unroll 5
        for (int i = 0; i < 25; i++) {
            ull xi2 = splat2(hv[i]);
            const ulonglong2* wv = (const ulonglong2*)(&sW[m][i * 28]);
#pragma unroll
            for (int j4 = 0; j4 < 7; j4++) {
                ulonglong2 w4 = wv[j4];
                acc[2 * j4]     = fma2(xi2, w4.x, acc[2 * j4]);
                acc[2 * j4 + 1] = fma2(xi2, w4.y, acc[2 * j4 + 1]);
            }
        }
        ull* o = (ull*)outs[m];
#pragma unroll
        for (int j2 = 0; j2 < 14; j2++) o[j2] = acc[j2];
    }
}

// ---------------- attention: one warp per node; direct softmax (round-9 version) ----------------
__global__ __launch_bounds__(128, 3) void k_attn(const float* __restrict__ We,
                                                 const float* __restrict__ be_, int l)
{
    __shared__ float sWe0[28], sWe1[28], sbe[28];
    if (threadIdx.x < 28) {
        int c = threadIdx.x;
        sWe0[c] = (c < 25) ? We[l * 50 + c]      : 0.f;
        sWe1[c] = (c < 25) ? We[l * 50 + 25 + c] : 0.f;
        sbe[c]  = (c < 25) ? be_[l * 25 + c]     : 0.f;
    }
    __syncthreads();
    int warp = threadIdx.x >> 5, lane = threadIdx.x & 31;
    int n = blockIdx.x * 4 + warp;
    if (n >= N_NODES) return;

    int beg = g_off[n], end = g_off[n + 1];
    float q[28];
    {
        const float4* qr = (const float4*)(g_q + (size_t)n * HPAD);
#pragma unroll
        for (int c4 = 0; c4 < 7; c4++) {
            float4 t = qr[c4];
            q[c4 * 4] = t.x; q[c4 * 4 + 1] = t.y; q[c4 * 4 + 2] = t.z; q[c4 * 4 + 3] = t.w;
        }
    }
    float acc[25], d[NH];
#pragma unroll
    for (int c = 0; c < 25; c++) acc[c] = 0.f;
#pragma unroll
    for (int hh = 0; hh < NH; hh++) d[hh] = 0.f;
    const float scale = 0.44721359549995794f;  // 1/sqrt(5)

    for (int base = beg; base < end; base += 32) {
        int idx = base + lane;
        if (idx < end) {
            float4 p = g_pay[idx];
            int src = __float_as_int(p.x);
            float eav = p.y, evv = p.z;
            const float4* kr = (const float4*)(g_k + (size_t)src * HPAD);
            const float4* vr = (const float4*)(g_v + (size_t)src * HPAD);
            float kk[28], vv[28];
#pragma unroll
            for (int c4 = 0; c4 < 7; c4++) {
                float4 t = kr[c4];
                kk[c4 * 4] = t.x; kk[c4 * 4 + 1] = t.y; kk[c4 * 4 + 2] = t.z; kk[c4 * 4 + 3] = t.w;
            }
#pragma unroll
            for (int c4 = 0; c4 < 7; c4++) {
                float4 t = vr[c4];
                vv[c4 * 4] = t.x; vv[c4 * 4 + 1] = t.y; vv[c4 * 4 + 2] = t.z; vv[c4 * 4 + 3] = t.w;
            }
            float al[NH] = {0.f, 0.f, 0.f, 0.f, 0.f};
#pragma unroll
            for (int c = 0; c < 25; c++) {
                float ee = sbe[c] + eav * sWe0[c] + evv * sWe1[c];
                al[c / 5] += q[c] * (kk[c] + ee);
            }
            float ex[NH];
#pragma unroll
            for (int hh = 0; hh < NH; hh++) {
                ex[hh] = __expf(al[hh] * scale);
                d[hh] += ex[hh];
            }
#pragma unroll
            for (int c = 0; c < 25; c++) {
                float ee = sbe[c] + eav * sWe0[c] + evv * sWe1[c];
                acc[c] += ex[c / 5] * (vv[c] + ee);
            }
        }
    }
#pragma unroll
    for (int hh = 0; hh < NH; hh++)
#pragma unroll
        for (int off = 16; off >= 1; off >>= 1)
            d[hh] += __shfl_xor_sync(0xffffffffu, d[hh], off);
#pragma unroll
    for (int c = 0; c < 25; c++)
#pragma unroll
        for (int off = 16; off >= 1; off >>= 1)
            acc[c] += __shfl_xor_sync(0xffffffffu, acc[c], off);
    if (lane == 0) {
#pragma unroll
        for (int c = 0; c < 25; c++)
            g_hn[(size_t)n * HPAD + c] =
                acc[c] / (d[c / 5] + 1e-16f) + g_sk[(size_t)n * HPAD + c];
    }
}

__global__ void k_out(const float* __restrict__ oW, const float* __restrict__ ob,
                      float* __restrict__ out) {
    __shared__ float sw[25];
    __shared__ float sb0;
    if (threadIdx.x < 25) sw[threadIdx.x] = oW[threadIdx.x];
    if (threadIdx.x == 0) sb0 = ob[0];
    __syncthreads();
    int n = blockIdx.x * blockDim.x + threadIdx.x;
    if (n >= N_NODES) return;
    float z = sb0;
#pragma unroll
    for (int c = 0; c < 25; c++) z += g_hn[(size_t)n * HPAD + c] * sw[c];
    out[n] = 1.f / (1.f + __expf(-z));
}

// ---------------- launcher ----------------
extern "C" void kernel_launch(void* const* d_in, const int* in_sizes, int n_in,
                              void* d_out, int out_size) {
    const float* x     = (const float*)d_in[0];
    const float* token = (const float*)d_in[1];
    const float* ea    = (const float*)d_in[2];
    const float* gum   = (const float*)d_in[3];
    const int* ei;
    int pb;
    if (in_sizes[4] == 2 * N_EDGES) {
        ei = (const int*)d_in[4];
        pb = 5;
    } else {
        ei = (const int*)d_in[n_in - 1];
        pb = 4;
    }
    const float* W0  = (const float*)d_in[pb + 0];
    const float* b0  = (const float*)d_in[pb + 1];
    const float* W1  = (const float*)d_in[pb + 2];
    const float* b1  = (const float*)d_in[pb + 3];
    const float* W2  = (const float*)d_in[pb + 4];
    const float* b2  = (const float*)d_in[pb + 5];
    const float* W3  = (const float*)d_in[pb + 6];
    const float* b3  = (const float*)d_in[pb + 7];
    const float* ilW = (const float*)d_in[pb + 8];
    const float* ilb = (const float*)d_in[pb + 9];
    const float* Wq  = (const float*)d_in[pb + 10];
    const float* bq  = (const float*)d_in[pb + 11];
    const float* Wk  = (const float*)d_in[pb + 12];
    const float* bk  = (const float*)d_in[pb + 13];
    const float* Wv  = (const float*)d_in[pb + 14];
    const float* bv  = (const float*)d_in[pb + 15];
    const float* We  = (const float*)d_in[pb + 16];
    const float* be  = (const float*)d_in[pb + 17];
    const float* Wsk = (const float*)d_in[pb + 18];
    const float* bsk = (const float*)d_in[pb + 19];
    const float* oW  = (const float*)d_in[pb + 20];
    const float* ob  = (const float*)d_in[pb + 21];

    int eb = (N_EDGES + 255) / 256;

    k_prep<<<eb, 256>>>(x, token, ilW, ilb, W0, ei);                       // 1
    k_scan1<<<SCAN_B, 1024>>>();                                          // 2
    k_scan3<<<SCAN_B, 1024>>>();                                          // 3 (also re-zeroes g_deg)
    k_mlp<<<N_EDGES / 64, 128>>>(W0, b0, W1, b1, W2, b2,
                                 W3, b3, ea, gum, ei);                    // 4 (profiled)
    for (int l = 0; l < 3; l++) {
        k_qkv<<<(N_NODES + 127) / 128, 128>>>(Wq, bq, Wk, bk, Wv, bv, Wsk, bsk, l);
        k_attn<<<(N_NODES + 3) / 4, 128>>>(We, be, l);
    }
    k_out<<<(N_NODES + 255) / 256, 256>>>(oW, ob, (float*)d_out);
}

// round 16
// speedup vs baseline: 1.3621x; 1.1505x over previous
#include <cuda_runtime.h>
#include <cuda_bf16.h>
#include <math.h>

#define N_NODES 100000
#define N_EDGES 3200000
#define HID 25
#define HPAD 32
#define NH 5
#define MH 50
#define MHP 52
#define ASTRIDE 64
#define SCAN_B 98
#define NODEB 391
#define NP 56
#define SSTR 57
#define WF_ENTRIES 1568   // 49 cells * 32 lanes per layer

typedef unsigned long long ull;

// ---------------- static device scratch (zero-initialized at module load) ----------------
__device__ __align__(16) float  g_hn [N_NODES * HPAD];
__device__ __align__(16) float  g_q  [N_NODES * HPAD];
__device__ __align__(16) float  g_k  [N_NODES * HPAD];
__device__ __align__(16) float  g_v  [N_NODES * HPAD];
__device__ __align__(16) float  g_sk [N_NODES * HPAD];
__device__ __align__(16) float  g_A  [N_NODES * ASTRIDE];
__device__ __align__(16) float  g_B  [N_NODES * ASTRIDE];
__device__ __align__(16) float2 g_W1f[WF_ENTRIES];   // fragment-ordered W1
__device__ __align__(16) float2 g_W2f[WF_ENTRIES];   // fragment-ordered W2
__device__ int    g_deg[N_NODES];          // invariant: zero at kernel_launch entry
__device__ int    g_off[N_NODES + 1];
__device__ int    g_cur[N_NODES];
__device__ int    g_bsum[SCAN_B];
__device__ float4 g_pay[N_EDGES];

__device__ __forceinline__ float gelu_f(float x) {
    return 0.5f * x * (1.0f + erff(x * 0.70710678118654752440f));
}
__device__ __forceinline__ void mma_tf32(float d[4],
                                         unsigned a0, unsigned a1, unsigned a2, unsigned a3,
                                         unsigned b0, unsigned b1) {
    asm volatile(
        "mma.sync.aligned.m16n8k8.row.col.f32.tf32.tf32.f32 "
        "{%0,%1,%2,%3}, {%4,%5,%6,%7}, {%8,%9}, {%0,%1,%2,%3};"
        : "+f"(d[0]), "+f"(d[1]), "+f"(d[2]), "+f"(d[3])
        : "r"(a0), "r"(a1), "r"(a2), "r"(a3), "r"(b0), "r"(b1));
}

// ---------------- launch 1: fused node-init + edge degree count + weight-frag build ----------------
__global__ __launch_bounds__(256) void k_prep(
    const float* __restrict__ x, const float* __restrict__ token,
    const float* __restrict__ ilW, const float* __restrict__ ilb,
    const float* __restrict__ W0, const float* __restrict__ W1,
    const float* __restrict__ W2, const int* __restrict__ ei)
{
    int gid = blockIdx.x * 256 + threadIdx.x;
    if (gid < N_EDGES) atomicAdd(&g_deg[ei[N_EDGES + gid]], 1);
    if (blockIdx.x >= NODEB) {
        // spare blocks build the fragment-ordered weight tables (2*1568 float2)
        int t = (blockIdx.x - NODEB) * 256 + threadIdx.x;
        if (t < 2 * WF_ENTRIES) {
            int L = t / WF_ENTRIES;
            int r = t - L * WF_ENTRIES;
            int cell = r >> 5, lane = r & 31;
            int kk = cell / 7, nn = cell - kk * 7;
            int tg = lane & 3, gr = lane >> 2;
            int r0 = kk * 8 + tg, c = nn * 8 + gr;
            const float* W = L ? W2 : W1;
            float v0 = (r0 < MH && c < MH) ? W[r0 * MH + c] : 0.f;
            float v1 = (r0 + 4 < MH && c < MH) ? W[(r0 + 4) * MH + c] : 0.f;
            (L ? g_W2f : g_W1f)[cell * 32 + lane] = make_float2(v0, v1);
        }
        return;
    }

    __shared__ __align__(16) float sIl[6 * 28];
    __shared__ float sIb[28];
    __shared__ __align__(16) float sW0[12 * MHP];
    for (int t = threadIdx.x; t < 6 * 28; t += 256) {
        int i = t / 28, j = t % 28;
        sIl[t] = (j < HID) ? ilW[i * HID + j] : 0.f;
    }
    for (int t = threadIdx.x; t < 28; t += 256) sIb[t] = (t < HID) ? ilb[t] : 0.f;
    for (int t = threadIdx.x; t < 12 * MHP; t += 256) {
        int i = t / MHP, j = t % MHP;
        sW0[t] = (j < MH) ? W0[i * MH + j] : 0.f;
    }
    __syncthreads();
    int n = gid;
    if (n >= N_NODES) return;
    float xt[6];
    xt[0] = x[n];
#pragma unroll
    for (int i = 0; i < 5; i++) xt[1 + i] = token[n * 5 + i];

    {
        float acc[28];
#pragma unroll
        for (int j = 0; j < 28; j++) acc[j] = sIb[j];
#pragma unroll
        for (int i = 0; i < 6; i++) {
            float xi = xt[i];
#pragma unroll
            for (int j = 0; j < 28; j++) acc[j] += xi * sIl[i * 28 + j];
        }
        float4* ho = (float4*)(g_hn + (size_t)n * HPAD);
#pragma unroll
        for (int j4 = 0; j4 < 7; j4++)
            ho[j4] = make_float4(acc[j4 * 4], acc[j4 * 4 + 1], acc[j4 * 4 + 2], acc[j4 * 4 + 3]);
        ho[7] = make_float4(0.f, 0.f, 0.f, 0.f);
    }
    {
        float acc[MHP];
#pragma unroll
        for (int j = 0; j < MHP; j++) acc[j] = 0.f;
#pragma unroll
        for (int i = 0; i < 6; i++) {
            float xi = xt[i];
#pragma unroll
            for (int j = 0; j < MHP; j++) acc[j] += xi * sW0[i * MHP + j];
        }
        float4* ao = (float4*)(g_A + (size_t)n * ASTRIDE);
#pragma unroll
        for (int j4 = 0; j4 < 13; j4++)
            ao[j4] = make_float4(acc[j4 * 4], acc[j4 * 4 + 1], acc[j4 * 4 + 2], acc[j4 * 4 + 3]);
#pragma unroll
        for (int j = 0; j < MHP; j++) acc[j] = 0.f;
#pragma unroll
        for (int i = 0; i < 6; i++) {
            float xi = xt[i];
#pragma unroll
            for (int j = 0; j < MHP; j++) acc[j] += xi * sW0[(6 + i) * MHP + j];
        }
        float4* bo = (float4*)(g_B + (size_t)n * ASTRIDE);
#pragma unroll
        for (int j4 = 0; j4 < 13; j4++)
            bo[j4] = make_float4(acc[j4 * 4], acc[j4 * 4 + 1], acc[j4 * 4 + 2], acc[j4 * 4 + 3]);
    }
}

// ---------------- launch 2/3: scan ----------------
__global__ void k_scan1() {
    __shared__ int s[1024];
    int i = blockIdx.x * 1024 + threadIdx.x;
    int v = (i < N_NODES) ? g_deg[i] : 0;
    s[threadIdx.x] = v;
    __syncthreads();
    for (int st = 1; st < 1024; st <<= 1) {
        int t = (threadIdx.x >= st) ? s[threadIdx.x - st] : 0;
        __syncthreads();
        s[threadIdx.x] += t;
        __syncthreads();
    }
    if (i < N_NODES) g_off[i + 1] = s[threadIdx.x];
    if (threadIdx.x == 1023) g_bsum[blockIdx.x] = s[1023];
}

// adds block prefix, emits g_cur, and re-zeroes g_deg (its last consumer)
__global__ void k_scan3() {
    __shared__ int pre;
    if (threadIdx.x < 32) {
        int lane = threadIdx.x;
        int tot = 0;
#pragma unroll
        for (int j = 0; j < 4; j++) {
            int idx = lane * 4 + j;
            tot += (idx < SCAN_B && idx < (int)blockIdx.x) ? g_bsum[idx] : 0;
        }
        int run = tot;
#pragma unroll
        for (int off = 1; off < 32; off <<= 1) {
            int t = __shfl_up_sync(0xffffffffu, run, off);
            if (lane >= off) run += t;
        }
        if (lane == 31) pre = run;
    }
    __syncthreads();
    int i = blockIdx.x * 1024 + threadIdx.x;
    if (i < N_NODES) {
        int off = g_off[i + 1] + pre;
        g_off[i + 1] = off;
        g_cur[i] = off - g_deg[i];
        g_deg[i] = 0;
    }
    if (blockIdx.x == 0 && threadIdx.x == 0) g_off[0] = 0;
}

// ---------------- launch 4 (profiled): edge MLP, single-pass tf32 mma,
// B fragments streamed from L1-resident fragment-ordered global tables ----------------
__global__ __launch_bounds__(128, 4) void k_mlp(
    const float* __restrict__ W0, const float* __restrict__ b0,
    const float* __restrict__ b1, const float* __restrict__ b2,
    const float* __restrict__ W3, const float* __restrict__ b3,
    const float* __restrict__ ea_arr, const float* __restrict__ gum,
    const int* __restrict__ ei)
{
    __shared__ __align__(16) float sW0c[NP], sb0[NP], sb1[NP], sb2[NP];
    __shared__ __align__(16) float sW3[112];
    __shared__ float sb3[2];
    __shared__ __align__(16) float stage[64 * SSTR];

    for (int t = threadIdx.x; t < NP; t += 128) {
        sW0c[t] = (t < MH) ? W0[12 * MH + t] : 0.f;
        sb0[t]  = (t < MH) ? b0[t] : 0.f;
        sb1[t]  = (t < MH) ? b1[t] : 0.f;
        sb2[t]  = (t < MH) ? b2[t] : 0.f;
        sW3[2 * t]     = (t < MH) ? W3[t * 2 + 0] : 0.f;
        sW3[2 * t + 1] = (t < MH) ? W3[t * 2 + 1] : 0.f;
    }
    if (threadIdx.x < 2) sb3[threadIdx.x] = b3[threadIdx.x];
    __syncthreads();

    const int tid = threadIdx.x;
    const int eBase = blockIdx.x * 64;

    {   // layer 0: two threads per edge
        int r = tid >> 1, half = tid & 1;
        int e = eBase + r;
        int src = ei[e], dst = ei[N_EDGES + e];
        float ea = ea_arr[e];
        const float4* Ar  = (const float4*)(g_A + (size_t)src * ASTRIDE) + half * 7;
        const float4* Br  = (const float4*)(g_B + (size_t)dst * ASTRIDE) + half * 7;
        const float4* b0p = (const float4*)sb0  + half * 7;
        const float4* wcp = (const float4*)sW0c + half * 7;
        float* srow = stage + r * SSTR + half * 28;
#pragma unroll
        for (int j4 = 0; j4 < 7; j4++) {
            float4 av = Ar[j4], bv = Br[j4], bb = b0p[j4], wc = wcp[j4];
            srow[j4 * 4 + 0] = gelu_f(bb.x + av.x + bv.x + ea * wc.x);
            srow[j4 * 4 + 1] = gelu_f(bb.y + av.y + bv.y + ea * wc.y);
            srow[j4 * 4 + 2] = gelu_f(bb.z + av.z + bv.z + ea * wc.z);
            srow[j4 * 4 + 3] = gelu_f(bb.w + av.w + bv.w + ea * wc.w);
        }
    }
    __syncwarp();

    const int w = tid >> 5, lane = tid & 31;
    const int gr = lane >> 2, tg = lane & 3;
    float* Sw = stage + (w * 16) * SSTR;
    const float* bl[2] = { sb1, sb2 };

#pragma unroll
    for (int L = 0; L < 2; L++) {
        const float2* __restrict__ Bf = (L ? g_W2f : g_W1f) + lane;
        float d[7][4];
#pragma unroll
        for (int nn = 0; nn < 7; nn++)
#pragma unroll
            for (int q = 0; q < 4; q++) d[nn][q] = 0.f;

#pragma unroll
        for (int kk = 0; kk < 7; kk++) {
            int c0 = kk * 8 + tg;
            unsigned a0 = __float_as_uint(Sw[gr * SSTR + c0]);
            unsigned a1 = __float_as_uint(Sw[(gr + 8) * SSTR + c0]);
            unsigned a2 = __float_as_uint(Sw[gr * SSTR + c0 + 4]);
            unsigned a3 = __float_as_uint(Sw[(gr + 8) * SSTR + c0 + 4]);
#pragma unroll
            for (int nn = 0; nn < 7; nn++) {
                float2 b = Bf[(kk * 7 + nn) * 32];   // LDG.64, L1-broadcast across blocks
                mma_tf32(d[nn], a0, a1, a2, a3,
                         __float_as_uint(b.x), __float_as_uint(b.y));
            }
        }
        __syncwarp();
#pragma unroll
        for (int nn = 0; nn < 7; nn++) {
            int cA = nn * 8 + 2 * tg, cB = cA + 1;
            float bA = bl[L][cA], bB = bl[L][cB];
            Sw[gr * SSTR + cA]       = gelu_f(d[nn][0] + bA);
            Sw[gr * SSTR + cB]       = gelu_f(d[nn][1] + bB);
            Sw[(gr + 8) * SSTR + cA] = gelu_f(d[nn][2] + bA);
            Sw[(gr + 8) * SSTR + cB] = gelu_f(d[nn][3] + bB);
        }
        __syncwarp();
    }

    {   // logits (50 -> 2), lane pairs share an edge
        int r = w * 16 + (lane >> 1);
        int half = lane & 1;
        const float* hrow = stage + r * SSTR + half * 25;
        float l0 = 0.f, l1 = 0.f;
#pragma unroll
        for (int i = 0; i < 25; i++) {
            float h = hrow[i];
            int j = half * 25 + i;
            l0 += h * sW3[2 * j];
            l1 += h * sW3[2 * j + 1];
        }
        l0 += __shfl_xor_sync(0xffffffffu, l0, 1);
        l1 += __shfl_xor_sync(0xffffffffu, l1, 1);
        if (half == 0) {
            int e = eBase + r;
            float g0 = gum[2 * e], g1 = gum[2 * e + 1];
            float ev = (l1 + sb3[1] + g1 > l0 + sb3[0] + g0) ? 1.f : 0.f;
            int src = ei[e], dst = ei[N_EDGES + e];
            float ea = ea_arr[e];
            int pos = atomicAdd(&g_cur[dst], 1);
            g_pay[pos] = make_float4(__int_as_float(src), ea, ev, 0.f);
        }
    }
}

// ---------------- f32x2 helpers for node kernels ----------------
__device__ __forceinline__ ull splat2(float x) {
    ull r; unsigned xi = __float_as_uint(x);
    asm("mov.b64 %0, {%1, %1};" : "=l"(r) : "r"(xi));
    return r;
}
__device__ __forceinline__ ull fma2(ull a, ull b, ull c) {
    ull d; asm("fma.rn.f32x2 %0, %1, %2, %3;" : "=l"(d) : "l"(a), "l"(b), "l"(c));
    return d;
}

// ---------------- per-layer node transforms: q, k, v, skip ----------------
__global__ __launch_bounds__(128) void k_qkv(
    const float* __restrict__ Wq, const float* __restrict__ bq,
    const float* __restrict__ Wk, const float* __restrict__ bk,
    const float* __restrict__ Wv, const float* __restrict__ bv,
    const float* __restrict__ Ws, const float* __restrict__ bs, int l)
{
    __shared__ __align__(16) float sW[4][25 * 28];
    __shared__ __align__(16) float sb[4][28];
    const float* Wl[4] = { Wq + l * 625, Wk + l * 625, Wv + l * 625, Ws + l * 625 };
    const float* bl[4] = { bq + l * 25,  bk + l * 25,  bv + l * 25,  bs + l * 25 };
    for (int m = 0; m < 4; m++) {
        for (int t = threadIdx.x; t < 25 * 28; t += 128) {
            int i = t / 28, j = t % 28;
            sW[m][t] = (j < 25) ? Wl[m][i * 25 + j] : 0.f;
        }
        for (int t = threadIdx.x; t < 28; t += 128)
            sb[m][t] = (t < 25) ? bl[m][t] : 0.f;
    }
    __syncthreads();
    int n = blockIdx.x * 128 + threadIdx.x;
    if (n >= N_NODES) return;
    float hv[25];
#pragma unroll
    for (int c = 0; c < 25; c++) hv[c] = g_hn[(size_t)n * HPAD + c];
    float* outs[4] = { g_q + (size_t)n * HPAD, g_k + (size_t)n * HPAD,
                       g_v + (size_t)n * HPAD, g_sk + (size_t)n * HPAD };
#pragma unroll
    for (int m = 0; m < 4; m++) {
        ull acc[14];
        const ull* sbp = (const ull*)sb[m];
#pragma unroll
        for (int j2 = 0; j2 < 14; j2++) acc[j2] = sbp[j2];
#pragma unroll 5
        for (int i = 0; i < 25; i++) {
            ull xi2 = splat2(hv[i]);
            const ulonglong2* wv = (const ulonglong2*)(&sW[m][i * 28]);
#pragma unroll
            for (int j4 = 0; j4 < 7; j4++) {
                ulonglong2 w4 = wv[j4];
                acc[2 * j4]     = fma2(xi2, w4.x, acc[2 * j4]);
                acc[2 * j4 + 1] = fma2(xi2, w4.y, acc[2 * j4 + 1]);
            }
        }
        ull* o = (ull*)outs[m];
#pragma unroll
        for (int j2 = 0; j2 < 14; j2++) o[j2] = acc[j2];
    }
}

// ---------------- attention: one warp per node; direct softmax (round-9 version) ----------------
__global__ __launch_bounds__(128, 3) void k_attn(const float* __restrict__ We,
                                                 const float* __restrict__ be_, int l)
{
    __shared__ float sWe0[28], sWe1[28], sbe[28];
    if (threadIdx.x < 28) {
        int c = threadIdx.x;
        sWe0[c] = (c < 25) ? We[l * 50 + c]      : 0.f;
        sWe1[c] = (c < 25) ? We[l * 50 + 25 + c] : 0.f;
        sbe[c]  = (c < 25) ? be_[l * 25 + c]     : 0.f;
    }
    __syncthreads();
    int warp = threadIdx.x >> 5, lane = threadIdx.x & 31;
    int n = blockIdx.x * 4 + warp;
    if (n >= N_NODES) return;

    int beg = g_off[n], end = g_off[n + 1];
    float q[28];
    {
        const float4* qr = (const float4*)(g_q + (size_t)n * HPAD);
#pragma unroll
        for (int c4 = 0; c4 < 7; c4++) {
            float4 t = qr[c4];
            q[c4 * 4] = t.x; q[c4 * 4 + 1] = t.y; q[c4 * 4 + 2] = t.z; q[c4 * 4 + 3] = t.w;
        }
    }
    float acc[25], d[NH];
#pragma unroll
    for (int c = 0; c < 25; c++) acc[c] = 0.f;
#pragma unroll
    for (int hh = 0; hh < NH; hh++) d[hh] = 0.f;
    const float scale = 0.44721359549995794f;  // 1/sqrt(5)

    for (int base = beg; base < end; base += 32) {
        int idx = base + lane;
        if (idx < end) {
            float4 p = g_pay[idx];
            int src = __float_as_int(p.x);
            float eav = p.y, evv = p.z;
            const float4* kr = (const float4*)(g_k + (size_t)src * HPAD);
            const float4* vr = (const float4*)(g_v + (size_t)src * HPAD);
            float kk[28], vv[28];
#pragma unroll
            for (int c4 = 0; c4 < 7; c4++) {
                float4 t = kr[c4];
                kk[c4 * 4] = t.x; kk[c4 * 4 + 1] = t.y; kk[c4 * 4 + 2] = t.z; kk[c4 * 4 + 3] = t.w;
            }
#pragma unroll
            for (int c4 = 0; c4 < 7; c4++) {
                float4 t = vr[c4];
                vv[c4 * 4] = t.x; vv[c4 * 4 + 1] = t.y; vv[c4 * 4 + 2] = t.z; vv[c4 * 4 + 3] = t.w;
            }
            float al[NH] = {0.f, 0.f, 0.f, 0.f, 0.f};
#pragma unroll
            for (int c = 0; c < 25; c++) {
                float ee = sbe[c] + eav * sWe0[c] + evv * sWe1[c];
                al[c / 5] += q[c] * (kk[c] + ee);
            }
            float ex[NH];
#pragma unroll
            for (int hh = 0; hh < NH; hh++) {
                ex[hh] = __expf(al[hh] * scale);
                d[hh] += ex[hh];
            }
#pragma unroll
            for (int c = 0; c < 25; c++) {
                float ee = sbe[c] + eav * sWe0[c] + evv * sWe1[c];
                acc[c] += ex[c / 5] * (vv[c] + ee);
            }
        }
    }
#pragma unroll
    for (int hh = 0; hh < NH; hh++)
#pragma unroll
        for (int off = 16; off >= 1; off >>= 1)
            d[hh] += __shfl_xor_sync(0xffffffffu, d[hh], off);
#pragma unroll
    for (int c = 0; c < 25; c++)
#pragma unroll
        for (int off = 16; off >= 1; off >>= 1)
            acc[c] += __shfl_xor_sync(0xffffffffu, acc[c], off);
    if (lane == 0) {
#pragma unroll
        for (int c = 0; c < 25; c++)
            g_hn[(size_t)n * HPAD + c] =
                acc[c] / (d[c / 5] + 1e-16f) + g_sk[(size_t)n * HPAD + c];
    }
}

__global__ void k_out(const float* __restrict__ oW, const float* __restrict__ ob,
                      float* __restrict__ out) {
    __shared__ float sw[25];
    __shared__ float sb0;
    if (threadIdx.x < 25) sw[threadIdx.x] = oW[threadIdx.x];
    if (threadIdx.x == 0) sb0 = ob[0];
    __syncthreads();
    int n = blockIdx.x * blockDim.x + threadIdx.x;
    if (n >= N_NODES) return;
    float z = sb0;
#pragma unroll
    for (int c = 0; c < 25; c++) z += g_hn[(size_t)n * HPAD + c] * sw[c];
    out[n] = 1.f / (1.f + __expf(-z));
}

// ---------------- launcher ----------------
extern "C" void kernel_launch(void* const* d_in, const int* in_sizes, int n_in,
                              void* d_out, int out_size) {
    const float* x     = (const float*)d_in[0];
    const float* token = (const float*)d_in[1];
    const float* ea    = (const float*)d_in[2];
    const float* gum   = (const float*)d_in[3];
    const int* ei;
    int pb;
    if (in_sizes[4] == 2 * N_EDGES) {
        ei = (const int*)d_in[4];
        pb = 5;
    } else {
        ei = (const int*)d_in[n_in - 1];
        pb = 4;
    }
    const float* W0  = (const float*)d_in[pb + 0];
    const float* b0  = (const float*)d_in[pb + 1];
    const float* W1  = (const float*)d_in[pb + 2];
    const float* b1  = (const float*)d_in[pb + 3];
    const float* W2  = (const float*)d_in[pb + 4];
    const float* b2  = (const float*)d_in[pb + 5];
    const float* W3  = (const float*)d_in[pb + 6];
    const float* b3  = (const float*)d_in[pb + 7];
    const float* ilW = (const float*)d_in[pb + 8];
    const float* ilb = (const float*)d_in[pb + 9];
    const float* Wq  = (const float*)d_in[pb + 10];
    const float* bq  = (const float*)d_in[pb + 11];
    const float* Wk  = (const float*)d_in[pb + 12];
    const float* bk  = (const float*)d_in[pb + 13];
    const float* Wv  = (const float*)d_in[pb + 14];
    const float* bv  = (const float*)d_in[pb + 15];
    const float* We  = (const float*)d_in[pb + 16];
    const float* be  = (const float*)d_in[pb + 17];
    const float* Wsk = (const float*)d_in[pb + 18];
    const float* bsk = (const float*)d_in[pb + 19];
    const float* oW  = (const float*)d_in[pb + 20];
    const float* ob  = (const float*)d_in[pb + 21];

    int eb = (N_EDGES + 255) / 256;

    k_prep<<<eb, 256>>>(x, token, ilW, ilb, W0, W1, W2, ei);               // 1 (also builds W-frag tables)
    k_scan1<<<SCAN_B, 1024>>>();                                          // 2
    k_scan3<<<SCAN_B, 1024>>>();                                          // 3 (also re-zeroes g_deg)
    k_mlp<<<N_EDGES / 64, 128>>>(W0, b0, b1, b2, W3, b3, ea, gum, ei);    // 4 (profiled)
    for (int l = 0; l < 3; l++) {
        k_qkv<<<(N_NODES + 127) / 128, 128>>>(Wq, bq, Wk, bk, Wv, bv, Wsk, bsk, l);
        k_attn<<<(N_NODES + 3) / 4, 128>>>(We, be, l);
    }
    k_out<<<(N_NODES + 255) / 256, 256>>>(oW, ob, (float*)d_out);
}

// round 17
// speedup vs baseline: 1.3809x; 1.0138x over previous
#include <cuda_runtime.h>
#include <cuda_bf16.h>
#include <math.h>

#define N_NODES 100000
#define N_EDGES 3200000
#define HID 25
#define HPAD 32
#define NH 5
#define MH 50
#define MHP 52
#define ASTRIDE 64
#define SCAN_B 98
#define NODEB 391
#define NP 56
#define SSTR 60           // stage row stride: 16B-aligned rows, conflict-free frag access
#define WF_ENTRIES 1568   // 49 cells * 32 lanes per layer

typedef unsigned long long ull;

// ---------------- static device scratch (zero-initialized at module load) ----------------
__device__ __align__(16) float  g_hn [N_NODES * HPAD];
__device__ __align__(16) float  g_q  [N_NODES * HPAD];
__device__ __align__(16) float  g_k  [N_NODES * HPAD];
__device__ __align__(16) float  g_v  [N_NODES * HPAD];
__device__ __align__(16) float  g_sk [N_NODES * HPAD];
__device__ __align__(16) float  g_A  [N_NODES * ASTRIDE];
__device__ __align__(16) float  g_B  [N_NODES * ASTRIDE];
__device__ __align__(16) float2 g_W1f[WF_ENTRIES];   // fragment-ordered W1
__device__ __align__(16) float2 g_W2f[WF_ENTRIES];   // fragment-ordered W2
__device__ int    g_deg[N_NODES];          // invariant: zero at kernel_launch entry
__device__ int    g_off[N_NODES + 1];
__device__ int    g_cur[N_NODES];
__device__ int    g_bsum[SCAN_B];
__device__ float4 g_pay[N_EDGES];

__device__ __forceinline__ float gelu_f(float x) {
    return 0.5f * x * (1.0f + erff(x * 0.70710678118654752440f));
}
__device__ __forceinline__ void mma_tf32(float d[4],
                                         unsigned a0, unsigned a1, unsigned a2, unsigned a3,
                                         unsigned b0, unsigned b1) {
    asm volatile(
        "mma.sync.aligned.m16n8k8.row.col.f32.tf32.tf32.f32 "
        "{%0,%1,%2,%3}, {%4,%5,%6,%7}, {%8,%9}, {%0,%1,%2,%3};"
        : "+f"(d[0]), "+f"(d[1]), "+f"(d[2]), "+f"(d[3])
        : "r"(a0), "r"(a1), "r"(a2), "r"(a3), "r"(b0), "r"(b1));
}

// ---------------- launch 1: fused node-init + edge degree count + weight-frag build ----------------
__global__ __launch_bounds__(256) void k_prep(
    const float* __restrict__ x, const float* __restrict__ token,
    const float* __restrict__ ilW, const float* __restrict__ ilb,
    const float* __restrict__ W0, const float* __restrict__ W1,
    const float* __restrict__ W2, const int* __restrict__ ei)
{
    int gid = blockIdx.x * 256 + threadIdx.x;
    if (gid < N_EDGES) atomicAdd(&g_deg[ei[N_EDGES + gid]], 1);
    if (blockIdx.x >= NODEB) {
        int t = (blockIdx.x - NODEB) * 256 + threadIdx.x;
        if (t < 2 * WF_ENTRIES) {
            int L = t / WF_ENTRIES;
            int r = t - L * WF_ENTRIES;
            int cell = r >> 5, lane = r & 31;
            int kk = cell / 7, nn = cell - kk * 7;
            int tg = lane & 3, gr = lane >> 2;
            int r0 = kk * 8 + tg, c = nn * 8 + gr;
            const float* W = L ? W2 : W1;
            float v0 = (r0 < MH && c < MH) ? W[r0 * MH + c] : 0.f;
            float v1 = (r0 + 4 < MH && c < MH) ? W[(r0 + 4) * MH + c] : 0.f;
            (L ? g_W2f : g_W1f)[cell * 32 + lane] = make_float2(v0, v1);
        }
        return;
    }

    __shared__ __align__(16) float sIl[6 * 28];
    __shared__ float sIb[28];
    __shared__ __align__(16) float sW0[12 * MHP];
    for (int t = threadIdx.x; t < 6 * 28; t += 256) {
        int i = t / 28, j = t % 28;
        sIl[t] = (j < HID) ? ilW[i * HID + j] : 0.f;
    }
    for (int t = threadIdx.x; t < 28; t += 256) sIb[t] = (t < HID) ? ilb[t] : 0.f;
    for (int t = threadIdx.x; t < 12 * MHP; t += 256) {
        int i = t / MHP, j = t % MHP;
        sW0[t] = (j < MH) ? W0[i * MH + j] : 0.f;
    }
    __syncthreads();
    int n = gid;
    if (n >= N_NODES) return;
    float xt[6];
    xt[0] = x[n];
#pragma unroll
    for (int i = 0; i < 5; i++) xt[1 + i] = token[n * 5 + i];

    {
        float acc[28];
#pragma unroll
        for (int j = 0; j < 28; j++) acc[j] = sIb[j];
#pragma unroll
        for (int i = 0; i < 6; i++) {
            float xi = xt[i];
#pragma unroll
            for (int j = 0; j < 28; j++) acc[j] += xi * sIl[i * 28 + j];
        }
        float4* ho = (float4*)(g_hn + (size_t)n * HPAD);
#pragma unroll
        for (int j4 = 0; j4 < 7; j4++)
            ho[j4] = make_float4(acc[j4 * 4], acc[j4 * 4 + 1], acc[j4 * 4 + 2], acc[j4 * 4 + 3]);
        ho[7] = make_float4(0.f, 0.f, 0.f, 0.f);
    }
    {
        float acc[MHP];
#pragma unroll
        for (int j = 0; j < MHP; j++) acc[j] = 0.f;
#pragma unroll
        for (int i = 0; i < 6; i++) {
            float xi = xt[i];
#pragma unroll
            for (int j = 0; j < MHP; j++) acc[j] += xi * sW0[i * MHP + j];
        }
        float4* ao = (float4*)(g_A + (size_t)n * ASTRIDE);
#pragma unroll
        for (int j4 = 0; j4 < 13; j4++)
            ao[j4] = make_float4(acc[j4 * 4], acc[j4 * 4 + 1], acc[j4 * 4 + 2], acc[j4 * 4 + 3]);
#pragma unroll
        for (int j = 0; j < MHP; j++) acc[j] = 0.f;
#pragma unroll
        for (int i = 0; i < 6; i++) {
            float xi = xt[i];
#pragma unroll
            for (int j = 0; j < MHP; j++) acc[j] += xi * sW0[(6 + i) * MHP + j];
        }
        float4* bo = (float4*)(g_B + (size_t)n * ASTRIDE);
#pragma unroll
        for (int j4 = 0; j4 < 13; j4++)
            bo[j4] = make_float4(acc[j4 * 4], acc[j4 * 4 + 1], acc[j4 * 4 + 2], acc[j4 * 4 + 3]);
    }
}

// ---------------- launch 2/3: scan ----------------
__global__ void k_scan1() {
    __shared__ int s[1024];
    int i = blockIdx.x * 1024 + threadIdx.x;
    int v = (i < N_NODES) ? g_deg[i] : 0;
    s[threadIdx.x] = v;
    __syncthreads();
    for (int st = 1; st < 1024; st <<= 1) {
        int t = (threadIdx.x >= st) ? s[threadIdx.x - st] : 0;
        __syncthreads();
        s[threadIdx.x] += t;
        __syncthreads();
    }
    if (i < N_NODES) g_off[i + 1] = s[threadIdx.x];
    if (threadIdx.x == 1023) g_bsum[blockIdx.x] = s[1023];
}

// adds block prefix, emits g_cur, and re-zeroes g_deg (its last consumer)
__global__ void k_scan3() {
    __shared__ int pre;
    if (threadIdx.x < 32) {
        int lane = threadIdx.x;
        int tot = 0;
#pragma unroll
        for (int j = 0; j < 4; j++) {
            int idx = lane * 4 + j;
            tot += (idx < SCAN_B && idx < (int)blockIdx.x) ? g_bsum[idx] : 0;
        }
        int run = tot;
#pragma unroll
        for (int off = 1; off < 32; off <<= 1) {
            int t = __shfl_up_sync(0xffffffffu, run, off);
            if (lane >= off) run += t;
        }
        if (lane == 31) pre = run;
    }
    __syncthreads();
    int i = blockIdx.x * 1024 + threadIdx.x;
    if (i < N_NODES) {
        int off = g_off[i + 1] + pre;
        g_off[i + 1] = off;
        g_cur[i] = off - g_deg[i];
        g_deg[i] = 0;
    }
    if (blockIdx.x == 0 && threadIdx.x == 0) g_off[0] = 0;
}

// ---------------- launch 4 (profiled): edge MLP, single-pass tf32 mma,
// vectorized stage traffic (SSTR=60: aligned rows, conflict-free banks) ----------------
__global__ __launch_bounds__(128, 4) void k_mlp(
    const float* __restrict__ W0, const float* __restrict__ b0,
    const float* __restrict__ b1, const float* __restrict__ b2,
    const float* __restrict__ W3, const float* __restrict__ b3,
    const float* __restrict__ ea_arr, const float* __restrict__ gum,
    const int* __restrict__ ei)
{
    __shared__ __align__(16) float sW0c[NP], sb0[NP], sb1[NP], sb2[NP];
    __shared__ __align__(16) float sW3[112];
    __shared__ float sb3[2];
    __shared__ __align__(16) float stage[64 * SSTR];

    for (int t = threadIdx.x; t < NP; t += 128) {
        sW0c[t] = (t < MH) ? W0[12 * MH + t] : 0.f;
        sb0[t]  = (t < MH) ? b0[t] : 0.f;
        sb1[t]  = (t < MH) ? b1[t] : 0.f;
        sb2[t]  = (t < MH) ? b2[t] : 0.f;
        sW3[2 * t]     = (t < MH) ? W3[t * 2 + 0] : 0.f;
        sW3[2 * t + 1] = (t < MH) ? W3[t * 2 + 1] : 0.f;
    }
    if (threadIdx.x < 2) sb3[threadIdx.x] = b3[threadIdx.x];
    __syncthreads();

    const int tid = threadIdx.x;
    const int eBase = blockIdx.x * 64;

    {   // layer 0: two threads per edge; float4 stores (7 STS.128/thread)
        int r = tid >> 1, half = tid & 1;
        int e = eBase + r;
        int src = ei[e], dst = ei[N_EDGES + e];
        float ea = ea_arr[e];
        const float4* Ar  = (const float4*)(g_A + (size_t)src * ASTRIDE) + half * 7;
        const float4* Br  = (const float4*)(g_B + (size_t)dst * ASTRIDE) + half * 7;
        const float4* b0p = (const float4*)sb0  + half * 7;
        const float4* wcp = (const float4*)sW0c + half * 7;
        float4* srow = (float4*)(stage + r * SSTR + half * 28);
#pragma unroll
        for (int j4 = 0; j4 < 7; j4++) {
            float4 av = Ar[j4], bv = Br[j4], bb = b0p[j4], wc = wcp[j4];
            srow[j4] = make_float4(gelu_f(bb.x + av.x + bv.x + ea * wc.x),
                                   gelu_f(bb.y + av.y + bv.y + ea * wc.y),
                                   gelu_f(bb.z + av.z + bv.z + ea * wc.z),
                                   gelu_f(bb.w + av.w + bv.w + ea * wc.w));
        }
    }
    __syncwarp();

    const int w = tid >> 5, lane = tid & 31;
    const int gr = lane >> 2, tg = lane & 3;
    float* Sw = stage + (w * 16) * SSTR;
    const float* bl[2] = { sb1, sb2 };

#pragma unroll
    for (int L = 0; L < 2; L++) {
        const float2* __restrict__ Bf = (L ? g_W2f : g_W1f) + lane;
        float d[7][4];
#pragma unroll
        for (int nn = 0; nn < 7; nn++)
#pragma unroll
            for (int q = 0; q < 4; q++) d[nn][q] = 0.f;

#pragma unroll
        for (int kk = 0; kk < 7; kk++) {
            int c0 = kk * 8 + tg;
            unsigned a0 = __float_as_uint(Sw[gr * SSTR + c0]);
            unsigned a1 = __float_as_uint(Sw[(gr + 8) * SSTR + c0]);
            unsigned a2 = __float_as_uint(Sw[gr * SSTR + c0 + 4]);
            unsigned a3 = __float_as_uint(Sw[(gr + 8) * SSTR + c0 + 4]);
#pragma unroll
            for (int nn = 0; nn < 7; nn++) {
                float2 b = Bf[(kk * 7 + nn) * 32];   // LDG.64, L1-resident
                mma_tf32(d[nn], a0, a1, a2, a3,
                         __float_as_uint(b.x), __float_as_uint(b.y));
            }
        }
        __syncwarp();
        // epilogue: bias + gelu, float2 stores (8B-aligned: cA even)
#pragma unroll
        for (int nn = 0; nn < 7; nn++) {
            int cA = nn * 8 + 2 * tg;
            float bA = bl[L][cA], bB = bl[L][cA + 1];
            *(float2*)(Sw + gr * SSTR + cA) =
                make_float2(gelu_f(d[nn][0] + bA), gelu_f(d[nn][1] + bB));
            *(float2*)(Sw + (gr + 8) * SSTR + cA) =
                make_float2(gelu_f(d[nn][2] + bA), gelu_f(d[nn][3] + bB));
        }
        __syncwarp();
    }

    {   // logits (50 -> 2): halves split cols [0,28)/[28,56); float4 loads
        int r = w * 16 + (lane >> 1);
        int half = lane & 1;
        const float4* hrow = (const float4*)(stage + r * SSTR + half * 28);
        const float* w3h = sW3 + half * 56;          // interleaved pairs for cols half*28..+27
        float l0 = 0.f, l1 = 0.f;
#pragma unroll
        for (int j4 = 0; j4 < 7; j4++) {
            float4 h4 = hrow[j4];
            l0 += h4.x * w3h[8 * j4]     + h4.y * w3h[8 * j4 + 2]
                + h4.z * w3h[8 * j4 + 4] + h4.w * w3h[8 * j4 + 6];
            l1 += h4.x * w3h[8 * j4 + 1] + h4.y * w3h[8 * j4 + 3]
                + h4.z * w3h[8 * j4 + 5] + h4.w * w3h[8 * j4 + 7];
        }
        l0 += __shfl_xor_sync(0xffffffffu, l0, 1);
        l1 += __shfl_xor_sync(0xffffffffu, l1, 1);
        if (half == 0) {
            int e = eBase + r;
            float g0 = gum[2 * e], g1 = gum[2 * e + 1];
            float ev = (l1 + sb3[1] + g1 > l0 + sb3[0] + g0) ? 1.f : 0.f;
            int src = ei[e], dst = ei[N_EDGES + e];
            float ea = ea_arr[e];
            int pos = atomicAdd(&g_cur[dst], 1);
            g_pay[pos] = make_float4(__int_as_float(src), ea, ev, 0.f);
        }
    }
}

// ---------------- f32x2 helpers for node kernels ----------------
__device__ __forceinline__ ull splat2(float x) {
    ull r; unsigned xi = __float_as_uint(x);
    asm("mov.b64 %0, {%1, %1};" : "=l"(r) : "r"(xi));
    return r;
}
__device__ __forceinline__ ull fma2(ull a, ull b, ull c) {
    ull d; asm("fma.rn.f32x2 %0, %1, %2, %3;" : "=l"(d) : "l"(a), "l"(b), "l"(c));
    return d;
}

// ---------------- per-layer node transforms: q, k, v, skip ----------------
__global__ __launch_bounds__(128) void k_qkv(
    const float* __restrict__ Wq, const float* __restrict__ bq,
    const float* __restrict__ Wk, const float* __restrict__ bk,
    const float* __restrict__ Wv, const float* __restrict__ bv,
    const float* __restrict__ Ws, const float* __restrict__ bs, int l)
{
    __shared__ __align__(16) float sW[4][25 * 28];
    __shared__ __align__(16) float sb[4][28];
    const float* Wl[4] = { Wq + l * 625, Wk + l * 625, Wv + l * 625, Ws + l * 625 };
    const float* bl[4] = { bq + l * 25,  bk + l * 25,  bv + l * 25,  bs + l * 25 };
    for (int m = 0; m < 4; m++) {
        for (int t = threadIdx.x; t < 25 * 28; t += 128) {
            int i = t / 28, j = t % 28;
            sW[m][t] = (j < 25) ? Wl[m][i * 25 + j] : 0.f;
        }
        for (int t = threadIdx.x; t < 28; t += 128)
            sb[m][t] = (t < 25) ? bl[m][t] : 0.f;
    }
    __syncthreads();
    int n = blockIdx.x * 128 + threadIdx.x;
    if (n >= N_NODES) return;
    float hv[25];
#pragma unroll
    for (int c = 0; c < 25; c++) hv[c] = g_hn[(size_t)n * HPAD + c];
    float* outs[4] = { g_q + (size_t)n * HPAD, g_k + (size_t)n * HPAD,
                       g_v + (size_t)n * HPAD, g_sk + (size_t)n * HPAD };
#pragma unroll
    for (int m = 0; m < 4; m++) {
        ull acc[14];
        const ull* sbp = (const ull*)sb[m];
#pragma unroll
        for (int j2 = 0; j2 < 14; j2++) acc[j2] = sbp[j2];
#pragma unroll 5
        for (int i = 0; i < 25; i++) {
            ull xi2 = splat2(hv[i]);
            const ulonglong2* wv = (const ulonglong2*)(&sW[m][i * 28]);
#pragma unroll
            for (int j4 = 0; j4 < 7; j4++) {
                ulonglong2 w4 = wv[j4];
                acc[2 * j4]     = fma2(xi2, w4.x, acc[2 * j4]);
                acc[2 * j4 + 1] = fma2(xi2, w4.y, acc[2 * j4 + 1]);
            }
        }
        ull* o = (ull*)outs[m];
#pragma unroll
        for (int j2 = 0; j2 < 14; j2++) o[j2] = acc[j2];
    }
}

// ---------------- attention: one warp per node; direct softmax (round-9 version) ----------------
__global__ __launch_bounds__(128, 3) void k_attn(const float* __restrict__ We,
                                                 const float* __restrict__ be_, int l)
{
    __shared__ float sWe0[28], sWe1[28], sbe[28];
    if (threadIdx.x < 28) {
        int c = threadIdx.x;
        sWe0[c] = (c < 25) ? We[l * 50 + c]      : 0.f;
        sWe1[c] = (c < 25) ? We[l * 50 + 25 + c] : 0.f;
        sbe[c]  = (c < 25) ? be_[l * 25 + c]     : 0.f;
    }
    __syncthreads();
    int warp = threadIdx.x >> 5, lane = threadIdx.x & 31;
    int n = blockIdx.x * 4 + warp;
    if (n >= N_NODES) return;

    int beg = g_off[n], end = g_off[n + 1];
    float q[28];
    {
        const float4* qr = (const float4*)(g_q + (size_t)n * HPAD);
#pragma unroll
        for (int c4 = 0; c4 < 7; c4++) {
            float4 t = qr[c4];
            q[c4 * 4] = t.x; q[c4 * 4 + 1] = t.y; q[c4 * 4 + 2] = t.z; q[c4 * 4 + 3] = t.w;
        }
    }
    float acc[25], d[NH];
#pragma unroll
    for (int c = 0; c < 25; c++) acc[c] = 0.f;
#pragma unroll
    for (int hh = 0; hh < NH; hh++) d[hh] = 0.f;
    const float scale = 0.44721359549995794f;  // 1/sqrt(5)

    for (int base = beg; base < end; base += 32) {
        int idx = base + lane;
        if (idx < end) {
            float4 p = g_pay[idx];
            int src = __float_as_int(p.x);
            float eav = p.y, evv = p.z;
            const float4* kr = (const float4*)(g_k + (size_t)src * HPAD);
            const float4* vr = (const float4*)(g_v + (size_t)src * HPAD);
            float kk[28], vv[28];
#pragma unroll
            for (int c4 = 0; c4 < 7; c4++) {
                float4 t = kr[c4];
                kk[c4 * 4] = t.x; kk[c4 * 4 + 1] = t.y; kk[c4 * 4 + 2] = t.z; kk[c4 * 4 + 3] = t.w;
            }
#pragma unroll
            for (int c4 = 0; c4 < 7; c4++) {
                float4 t = vr[c4];
                vv[c4 * 4] = t.x; vv[c4 * 4 + 1] = t.y; vv[c4 * 4 + 2] = t.z; vv[c4 * 4 + 3] = t.w;
            }
            float al[NH] = {0.f, 0.f, 0.f, 0.f, 0.f};
#pragma unroll
            for (int c = 0; c < 25; c++) {
                float ee = sbe[c] + eav * sWe0[c] + evv * sWe1[c];
                al[c / 5] += q[c] * (kk[c] + ee);
            }
            float ex[NH];
#pragma unroll
            for (int hh = 0; hh < NH; hh++) {
                ex[hh] = __expf(al[hh] * scale);
                d[hh] += ex[hh];
            }
#pragma unroll
            for (int c = 0; c < 25; c++) {
                float ee = sbe[c] + eav * sWe0[c] + evv * sWe1[c];
                acc[c] += ex[c / 5] * (vv[c] + ee);
            }
        }
    }
#pragma unroll
    for (int hh = 0; hh < NH; hh++)
#pragma unroll
        for (int off = 16; off >= 1; off >>= 1)
            d[hh] += __shfl_xor_sync(0xffffffffu, d[hh], off);
#pragma unroll
    for (int c = 0; c < 25; c++)
#pragma unroll
        for (int off = 16; off >= 1; off >>= 1)
            acc[c] += __shfl_xor_sync(0xffffffffu, acc[c], off);
    if (lane == 0) {
#pragma unroll
        for (int c = 0; c < 25; c++)
            g_hn[(size_t)n * HPAD + c] =
                acc[c] / (d[c / 5] + 1e-16f) + g_sk[(size_t)n * HPAD + c];
    }
}

__global__ void k_out(const float* __restrict__ oW, const float* __restrict__ ob,
                      float* __restrict__ out) {
    __shared__ float sw[25];
    __shared__ float sb0;
    if (threadIdx.x < 25) sw[threadIdx.x] = oW[threadIdx.x];
    if (threadIdx.x == 0) sb0 = ob[0];
    __syncthreads();
    int n = blockIdx.x * blockDim.x + threadIdx.x;
    if (n >= N_NODES) return;
    float z = sb0;
#pragma unroll
    for (int c = 0; c < 25; c++) z += g_hn[(size_t)n * HPAD + c] * sw[c];
    out[n] = 1.f / (1.f + __expf(-z));
}

// ---------------- launcher ----------------
extern "C" void kernel_launch(void* const* d_in, const int* in_sizes, int n_in,
                              void* d_out, int out_size) {
    const float* x     = (const float*)d_in[0];
    const float* token = (const float*)d_in[1];
    const float* ea    = (const float*)d_in[2];
    const float* gum   = (const float*)d_in[3];
    const int* ei;
    int pb;
    if (in_sizes[4] == 2 * N_EDGES) {
        ei = (const int*)d_in[4];
        pb = 5;
    } else {
        ei = (const int*)d_in[n_in - 1];
        pb = 4;
    }
    const float* W0  = (const float*)d_in[pb + 0];
    const float* b0  = (const float*)d_in[pb + 1];
    const float* W1  = (const float*)d_in[pb + 2];
    const float* b1  = (const float*)d_in[pb + 3];
    const float* W2  = (const float*)d_in[pb + 4];
    const float* b2  = (const float*)d_in[pb + 5];
    const float* W3  = (const float*)d_in[pb + 6];
    const float* b3  = (const float*)d_in[pb + 7];
    const float* ilW = (const float*)d_in[pb + 8];
    const float* ilb = (const float*)d_in[pb + 9];
    const float* Wq  = (const float*)d_in[pb + 10];
    const float* bq  = (const float*)d_in[pb + 11];
    const float* Wk  = (const float*)d_in[pb + 12];
    const float* bk  = (const float*)d_in[pb + 13];
    const float* Wv  = (const float*)d_in[pb + 14];
    const float* bv  = (const float*)d_in[pb + 15];
    const float* We  = (const float*)d_in[pb + 16];
    const float* be  = (const float*)d_in[pb + 17];
    const float* Wsk = (const float*)d_in[pb + 18];
    const float* bsk = (const float*)d_in[pb + 19];
    const float* oW  = (const float*)d_in[pb + 20];
    const float* ob  = (const float*)d_in[pb + 21];

    int eb = (N_EDGES + 255) / 256;

    k_prep<<<eb, 256>>>(x, token, ilW, ilb, W0, W1, W2, ei);               // 1 (also builds W-frag tables)
    k_scan1<<<SCAN_B, 1024>>>();                                          // 2
    k_scan3<<<SCAN_B, 1024>>>();                                          // 3 (also re-zeroes g_deg)
    k_mlp<<<N_EDGES / 64, 128>>>(W0, b0, b1, b2, W3, b3, ea, gum, ei);    // 4 (profiled)
    for (int l = 0; l < 3; l++) {
        k_qkv<<<(N_NODES + 127) / 128, 128>>>(Wq, bq, Wk, bk, Wv, bv, Wsk, bsk, l);
        k_attn<<<(N_NODES + 3) / 4, 128>>>(We, be, l);
    }
    k_out<<<(N_NODES + 255) / 256, 256>>>(oW, ob, (float*)d_out);
}